// round 2
// baseline (speedup 1.0000x reference)
#include <cuda_runtime.h>
#include <cuda_bf16.h>
#include <math.h>

#define N_MAX   100000
#define E_MAX   1600000
#define ETOT_MAX (E_MAX + N_MAX)
#define G_NUM   64

// ---------------- scratch (device globals; no allocation) ----------------
__device__ float g_xall[N_MAX * 192];          // [xl(64) | xr(64) | xskip(64)] per node
__device__ float g_out[N_MAX * 64];            // GAT aggregation target (init = conv_bias)
__device__ float g_score[ETOT_MAX * 4];        // per-edge per-head score, then exp()
__device__ float g_smax[N_MAX * 4];            // segment max per (node, head)
__device__ float g_denom[N_MAX * 4];           // segment sum of exp per (node, head)
__device__ float g_sumM[G_NUM * 64];
__device__ float g_sumS[G_NUM * 64];
__device__ float g_varM[G_NUM * 64];
__device__ float g_varS[G_NUM * 64];
__device__ float g_cnt[G_NUM];

// ---------------- helpers ----------------
__device__ __forceinline__ void atomicMaxF(float* addr, float v) {
    if (v >= 0.0f) atomicMax((int*)addr, __float_as_int(v));
    else           atomicMin((unsigned int*)addr, __float_as_uint(v));
}

// ---------------- K0: init scratch ----------------
__global__ void k_init(const float* __restrict__ conv_bias, int N) {
    int i = blockIdx.x * blockDim.x + threadIdx.x;
    int total = N * 64;
    if (i < total) g_out[i] = conv_bias[i & 63];
    if (i < N * 4) { g_smax[i] = -3.4e38f; g_denom[i] = 0.0f; }
    if (i < G_NUM * 64) { g_sumM[i] = 0.f; g_sumS[i] = 0.f; g_varM[i] = 0.f; g_varS[i] = 0.f; }
    if (i < G_NUM) g_cnt[i] = 0.f;
}

// ---------------- K1: fused GEMM  C[N,192] = X[N,128] @ [Wl|Wr|Wskip] ----------------
__global__ __launch_bounds__(256) void k_gemm(
    const float* __restrict__ x,
    const float* __restrict__ Wl, const float* __restrict__ Wr,
    const float* __restrict__ Ws, const float* __restrict__ skip_b, int N)
{
    __shared__ float Xs[64 * 128];   // 32 KB
    int tid = threadIdx.x;
    int rowBase = blockIdx.x * 64;

    const float4* xg = (const float4*)x;
    #pragma unroll
    for (int i = tid; i < 64 * 32; i += 256) {
        int r = i >> 5, c4 = i & 31;
        int gr = rowBase + r;
        float4 v = (gr < N) ? xg[(size_t)gr * 32 + c4] : make_float4(0.f, 0.f, 0.f, 0.f);
        ((float4*)Xs)[i] = v;
    }
    __syncthreads();

    int tr = tid >> 5;     // warp id 0..7 -> row group
    int tc = tid & 31;     // lane -> col

    const float* wb[6];
    wb[0] = Wl + tc;       wb[1] = Wl + 32 + tc;
    wb[2] = Wr + tc;       wb[3] = Wr + 32 + tc;
    wb[4] = Ws + tc;       wb[5] = Ws + 32 + tc;

    float acc[8][6];
    #pragma unroll
    for (int i = 0; i < 8; i++)
        #pragma unroll
        for (int j = 0; j < 6; j++) acc[i][j] = 0.f;

    for (int k = 0; k < 128; k++) {
        float b[6];
        #pragma unroll
        for (int j = 0; j < 6; j++) b[j] = __ldg(wb[j] + k * 64);
        float a[8];
        #pragma unroll
        for (int i = 0; i < 8; i++) a[i] = Xs[(tr * 8 + i) * 128 + k];
        #pragma unroll
        for (int i = 0; i < 8; i++)
            #pragma unroll
            for (int j = 0; j < 6; j++) acc[i][j] = fmaf(a[i], b[j], acc[i][j]);
    }

    #pragma unroll
    for (int i = 0; i < 8; i++) {
        int gr = rowBase + tr * 8 + i;
        if (gr >= N) break;
        #pragma unroll
        for (int j = 0; j < 6; j++) {
            int c = tc + 32 * j;
            float v = acc[i][j];
            if (j >= 4) v += skip_b[c - 128];
            g_xall[(size_t)gr * 192 + c] = v;
        }
    }
}

// ---------------- K2a: edge scores + segment max (1 warp / edge) ----------------
__global__ __launch_bounds__(256) void k_edge_score(
    const int* __restrict__ ei, const float* __restrict__ att,
    int E, int ET)
{
    int gw = (blockIdx.x * blockDim.x + threadIdx.x) >> 5;
    if (gw >= ET) return;
    int lane = threadIdx.x & 31;

    int src, dst;
    if (gw < E) { src = ei[gw]; dst = ei[E + gw]; }
    else        { src = dst = gw - E; }

    const float* xlr = g_xall + (size_t)src * 192;       // xl row
    const float* xrr = g_xall + (size_t)dst * 192 + 64;  // xr row

    float v0 = xlr[lane]      + xrr[lane];
    float v1 = xlr[lane + 32] + xrr[lane + 32];
    v0 = v0 > 0.f ? v0 : 0.2f * v0;
    v1 = v1 > 0.f ? v1 : 0.2f * v1;
    float p0 = v0 * __ldg(att + lane);
    float p1 = v1 * __ldg(att + lane + 32);

    #pragma unroll
    for (int off = 8; off; off >>= 1) {
        p0 += __shfl_xor_sync(0xffffffffu, p0, off);
        p1 += __shfl_xor_sync(0xffffffffu, p1, off);
    }
    if ((lane & 15) == 0) {
        int h = lane >> 4;                      // 0 or 1
        g_score[(size_t)gw * 4 + h]     = p0;   // heads 0/1
        g_score[(size_t)gw * 4 + 2 + h] = p1;   // heads 2/3
        atomicMaxF(&g_smax[(size_t)dst * 4 + h],     p0);
        atomicMaxF(&g_smax[(size_t)dst * 4 + 2 + h], p1);
    }
}

// ---------------- K2b: exp + segment denom (1 thread / (edge,head)) ----------------
__global__ __launch_bounds__(256) void k_edge_exp(
    const int* __restrict__ ei, int E, int ET)
{
    int idx = blockIdx.x * blockDim.x + threadIdx.x;
    int e = idx >> 2;
    if (e >= ET) return;
    int h = idx & 3;
    int dst = (e < E) ? ei[E + e] : (e - E);
    float s = g_score[(size_t)e * 4 + h];
    float m = g_smax[(size_t)dst * 4 + h];
    float ex = expf(s - m);
    g_score[(size_t)e * 4 + h] = ex;
    atomicAdd(&g_denom[(size_t)dst * 4 + h], ex);
}

// ---------------- K2c: weighted scatter-aggregate (16 lanes / edge, red.v4) ----------------
__global__ __launch_bounds__(256) void k_edge_aggr(
    const int* __restrict__ ei, int E, int ET)
{
    int gw = (blockIdx.x * blockDim.x + threadIdx.x) >> 5;
    int lane = threadIdx.x & 31;
    int e = gw * 2 + (lane >> 4);
    if (e >= ET) return;
    int l = lane & 15;
    int ch4 = l << 2;          // channel group start (0,4,...,60)
    int h = l >> 2;            // head = ch4/16

    int src, dst;
    if (e < E) { src = ei[e]; dst = ei[E + e]; }
    else       { src = dst = e - E; }

    float alpha = g_score[(size_t)e * 4 + h] / g_denom[(size_t)dst * 4 + h];
    const float4 xv = *(const float4*)(g_xall + (size_t)src * 192 + ch4);
    float r0 = xv.x * alpha, r1 = xv.y * alpha, r2 = xv.z * alpha, r3 = xv.w * alpha;

    float* addr = g_out + (size_t)dst * 64 + ch4;
    asm volatile("red.global.add.v4.f32 [%0], {%1, %2, %3, %4};"
                 :: "l"(addr), "f"(r0), "f"(r1), "f"(r2), "f"(r3) : "memory");
}

// ---------------- K3: per-graph sums (run-length over sorted batch) ----------------
__global__ __launch_bounds__(256) void k_stats_sum(
    const int* __restrict__ batch, int N)
{
    int ch = threadIdx.x & 63;
    int slot = (blockIdx.x * blockDim.x + threadIdx.x) >> 6;
    int n0 = slot * 32;
    if (n0 >= N) return;
    int n1 = min(n0 + 32, N);

    float am = 0.f, as = 0.f, ac = 0.f;
    int curg = batch[n0];
    for (int n = n0; n < n1; n++) {
        int g = batch[n];
        if (g != curg) {
            atomicAdd(&g_sumM[curg * 64 + ch], am);
            atomicAdd(&g_sumS[curg * 64 + ch], as);
            if (ch == 0) atomicAdd(&g_cnt[curg], ac);
            am = as = ac = 0.f; curg = g;
        }
        am += g_out[(size_t)n * 64 + ch];
        as += g_xall[(size_t)n * 192 + 128 + ch];
        ac += 1.f;
    }
    atomicAdd(&g_sumM[curg * 64 + ch], am);
    atomicAdd(&g_sumS[curg * 64 + ch], as);
    if (ch == 0) atomicAdd(&g_cnt[curg], ac);
}

// ---------------- K4: per-graph variance sums ----------------
__global__ __launch_bounds__(256) void k_stats_var(
    const int* __restrict__ batch,
    const float* __restrict__ bn_ms, const float* __restrict__ sn_ms, int N)
{
    int ch = threadIdx.x & 63;
    int slot = (blockIdx.x * blockDim.x + threadIdx.x) >> 6;
    int n0 = slot * 32;
    if (n0 >= N) return;
    int n1 = min(n0 + 32, N);

    float msM = bn_ms[ch], msS = sn_ms[ch];
    int curg = batch[n0];
    float cnt = fmaxf(g_cnt[curg], 1.f);
    float meanM = g_sumM[curg * 64 + ch] / cnt;
    float meanS = g_sumS[curg * 64 + ch] / cnt;
    float avm = 0.f, avs = 0.f;

    for (int n = n0; n < n1; n++) {
        int g = batch[n];
        if (g != curg) {
            atomicAdd(&g_varM[curg * 64 + ch], avm);
            atomicAdd(&g_varS[curg * 64 + ch], avs);
            avm = avs = 0.f; curg = g;
            cnt = fmaxf(g_cnt[curg], 1.f);
            meanM = g_sumM[curg * 64 + ch] / cnt;
            meanS = g_sumS[curg * 64 + ch] / cnt;
        }
        float cm = g_out[(size_t)n * 64 + ch] - meanM * msM;
        float cs = g_xall[(size_t)n * 192 + 128 + ch] - meanS * msS;
        avm = fmaf(cm, cm, avm);
        avs = fmaf(cs, cs, avs);
    }
    atomicAdd(&g_varM[curg * 64 + ch], avm);
    atomicAdd(&g_varS[curg * 64 + ch], avs);
}

// ---------------- K5: normalize + residual + ELU ----------------
__global__ __launch_bounds__(256) void k_final(
    const int* __restrict__ batch,
    const float* __restrict__ bn_w, const float* __restrict__ bn_b, const float* __restrict__ bn_ms,
    const float* __restrict__ sn_w, const float* __restrict__ sn_b, const float* __restrict__ sn_ms,
    float* __restrict__ out, int N)
{
    int i = blockIdx.x * blockDim.x + threadIdx.x;
    if (i >= N * 64) return;
    int n = i >> 6, ch = i & 63;
    int g = batch[n];
    float cnt = fmaxf(g_cnt[g], 1.f);
    float mM = g_sumM[g * 64 + ch] / cnt;
    float vM = g_varM[g * 64 + ch] / cnt;
    float mS = g_sumS[g * 64 + ch] / cnt;
    float vS = g_varS[g * 64 + ch] / cnt;

    float cm = g_out[i] - mM * bn_ms[ch];
    float cs = g_xall[(size_t)n * 192 + 128 + ch] - mS * sn_ms[ch];
    float ym = bn_w[ch] * cm * rsqrtf(vM + 1e-5f) + bn_b[ch];
    float ys = sn_w[ch] * cs * rsqrtf(vS + 1e-5f) + sn_b[ch];
    float y = ym + ys;
    out[i] = (y > 0.f) ? y : expm1f(y);
}

// ---------------- launch ----------------
extern "C" void kernel_launch(void* const* d_in, const int* in_sizes, int n_in,
                              void* d_out, int out_size)
{
    const float* x         = (const float*)d_in[0];
    const int*   ei        = (const int*)d_in[1];
    const int*   batch     = (const int*)d_in[2];
    const float* Wl        = (const float*)d_in[3];
    const float* Wr        = (const float*)d_in[4];
    const float* att       = (const float*)d_in[5];
    const float* conv_bias = (const float*)d_in[6];
    const float* skip_W    = (const float*)d_in[7];
    const float* skip_b    = (const float*)d_in[8];
    const float* bn_w      = (const float*)d_in[9];
    const float* bn_b      = (const float*)d_in[10];
    const float* bn_ms     = (const float*)d_in[11];
    const float* sn_w      = (const float*)d_in[12];
    const float* sn_b      = (const float*)d_in[13];
    const float* sn_ms     = (const float*)d_in[14];
    float*       out       = (float*)d_out;

    int N  = in_sizes[0] / 128;
    int E  = in_sizes[1] / 2;
    int ET = E + N;

    {   // K0
        int total = N * 64;
        k_init<<<(total + 255) / 256, 256>>>(conv_bias, N);
    }
    {   // K1
        int blocks = (N + 63) / 64;
        k_gemm<<<blocks, 256>>>(x, Wl, Wr, skip_W, skip_b, N);
    }
    {   // K2a
        long long threads = (long long)ET * 32;
        k_edge_score<<<(unsigned)((threads + 255) / 256), 256>>>(ei, att, E, ET);
    }
    {   // K2b
        long long threads = (long long)ET * 4;
        k_edge_exp<<<(unsigned)((threads + 255) / 256), 256>>>(ei, E, ET);
    }
    {   // K2c
        long long warps = (ET + 1) / 2;
        long long threads = warps * 32;
        k_edge_aggr<<<(unsigned)((threads + 255) / 256), 256>>>(ei, E, ET);
    }
    {   // K3
        int slots = (N + 31) / 32;
        long long threads = (long long)slots * 64;
        k_stats_sum<<<(unsigned)((threads + 255) / 256), 256>>>(batch, N);
    }
    {   // K4
        int slots = (N + 31) / 32;
        long long threads = (long long)slots * 64;
        k_stats_var<<<(unsigned)((threads + 255) / 256), 256>>>(batch, bn_ms, sn_ms, N);
    }
    {   // K5
        int total = N * 64;
        k_final<<<(total + 255) / 256, 256>>>(batch, bn_w, bn_b, bn_ms,
                                              sn_w, sn_b, sn_ms, out, N);
    }
}

// round 3
// speedup vs baseline: 1.8119x; 1.8119x over previous
#include <cuda_runtime.h>
#include <cuda_bf16.h>
#include <math.h>

#define N_MAX   100000
#define E_MAX   1600000
#define G_NUM   64

typedef unsigned long long ull;

// ---------------- scratch (device globals; no allocation) ----------------
__device__ __align__(16) float g_xl[N_MAX * 64];
__device__ __align__(16) float g_xr[N_MAX * 64];
__device__ __align__(16) float g_xs[N_MAX * 64];
__device__ __align__(16) float g_out[N_MAX * 64];
__device__ int   g_deg[N_MAX];
__device__ int   g_off[N_MAX];
__device__ int   g_cur[N_MAX];
__device__ int   g_csr[E_MAX];
__device__ int   g_bsum[1024];
__device__ float g_sumM[G_NUM * 64];
__device__ float g_sqM [G_NUM * 64];
__device__ float g_sumS[G_NUM * 64];
__device__ float g_sqS [G_NUM * 64];
__device__ float g_cnt [G_NUM];

// ---------------- f32x2 helpers ----------------
__device__ __forceinline__ ull pack_dup(float a) {
    ull r; asm("mov.b64 %0, {%1, %1};" : "=l"(r) : "f"(a)); return r;
}
__device__ __forceinline__ void fma2(ull& d, ull a, ull b) {
    asm("fma.rn.f32x2 %0, %1, %2, %0;" : "+l"(d) : "l"(a), "l"(b));
}
__device__ __forceinline__ void unpack2(ull v, float& lo, float& hi) {
    asm("mov.b64 {%0, %1}, %2;" : "=f"(lo), "=f"(hi) : "l"(v));
}

// ---------------- K0: init ----------------
__global__ void k_init(int N) {
    int i = blockIdx.x * blockDim.x + threadIdx.x;
    if (i < N) g_deg[i] = 0;
    if (i < G_NUM * 64) { g_sumM[i] = 0.f; g_sqM[i] = 0.f; g_sumS[i] = 0.f; g_sqS[i] = 0.f; }
    if (i < G_NUM) g_cnt[i] = 0.f;
}

// ---------------- CSR build ----------------
__global__ void k_hist(const int* __restrict__ ei, int E) {
    int i = blockIdx.x * blockDim.x + threadIdx.x;
    if (i < E) atomicAdd(&g_deg[ei[E + i]], 1);
}

__global__ __launch_bounds__(1024) void k_scan1(int N) {
    __shared__ int s[1024];
    int tid = threadIdx.x;
    int i = blockIdx.x * 1024 + tid;
    int v = (i < N) ? g_deg[i] : 0;
    s[tid] = v;
    #pragma unroll
    for (int d = 1; d < 1024; d <<= 1) {
        __syncthreads();
        int t = (tid >= d) ? s[tid - d] : 0;
        __syncthreads();
        s[tid] += t;
    }
    __syncthreads();
    if (i < N) g_off[i] = s[tid] - v;         // exclusive, block-local
    if (tid == 1023) g_bsum[blockIdx.x] = s[1023];
}

__global__ __launch_bounds__(1024) void k_scan2(int nb) {
    __shared__ int s[1024];
    int tid = threadIdx.x;
    int v = (tid < nb) ? g_bsum[tid] : 0;
    s[tid] = v;
    #pragma unroll
    for (int d = 1; d < 1024; d <<= 1) {
        __syncthreads();
        int t = (tid >= d) ? s[tid - d] : 0;
        __syncthreads();
        s[tid] += t;
    }
    __syncthreads();
    if (tid < nb) g_bsum[tid] = s[tid] - v;   // exclusive
}

__global__ void k_scan3(int N) {
    int i = blockIdx.x * blockDim.x + threadIdx.x;
    if (i >= N) return;
    int o = g_off[i] + g_bsum[i >> 10];
    g_off[i] = o;
    g_cur[i] = o;
}

__global__ void k_fill(const int* __restrict__ ei, int E) {
    int i = blockIdx.x * blockDim.x + threadIdx.x;
    if (i >= E) return;
    int dst = ei[E + i];
    int pos = atomicAdd(&g_cur[dst], 1);
    g_csr[pos] = ei[i];
}

// ---------------- K1: fused GEMM via f32x2  [xl|xr|xs] = X @ [Wl|Wr|Ws] ----------------
__global__ __launch_bounds__(256) void k_gemm(
    const float* __restrict__ x,
    const float* __restrict__ Wl, const float* __restrict__ Wr,
    const float* __restrict__ Ws, const float* __restrict__ skip_b, int N)
{
    __shared__ float Xs[64 * 128];
    int tid = threadIdx.x;
    int rowBase = blockIdx.x * 64;

    const float4* xg = (const float4*)x;
    for (int i = tid; i < 64 * 32; i += 256) {
        int r = i >> 5, c4 = i & 31;
        int gr = rowBase + r;
        float4 v = (gr < N) ? __ldg(xg + (size_t)gr * 32 + c4) : make_float4(0.f, 0.f, 0.f, 0.f);
        ((float4*)Xs)[i] = v;
    }
    __syncthreads();

    int tr = tid >> 5, tc = tid & 31;
    const ull* wl64 = (const ull*)Wl;
    const ull* wr64 = (const ull*)Wr;
    const ull* ws64 = (const ull*)Ws;

    ull acc[8][3];
    #pragma unroll
    for (int i = 0; i < 8; i++)
        #pragma unroll
        for (int j = 0; j < 3; j++) acc[i][j] = 0ULL;

    for (int k = 0; k < 128; k += 4) {
        ull bl[4], br[4], bs[4];
        #pragma unroll
        for (int kk = 0; kk < 4; kk++) {
            bl[kk] = __ldg(wl64 + (k + kk) * 32 + tc);
            br[kk] = __ldg(wr64 + (k + kk) * 32 + tc);
            bs[kk] = __ldg(ws64 + (k + kk) * 32 + tc);
        }
        float4 av[8];
        #pragma unroll
        for (int i = 0; i < 8; i++)
            av[i] = *(const float4*)&Xs[(tr * 8 + i) * 128 + k];
        #pragma unroll
        for (int kk = 0; kk < 4; kk++) {
            #pragma unroll
            for (int i = 0; i < 8; i++) {
                float a = (kk == 0) ? av[i].x : (kk == 1) ? av[i].y : (kk == 2) ? av[i].z : av[i].w;
                ull ad = pack_dup(a);
                fma2(acc[i][0], ad, bl[kk]);
                fma2(acc[i][1], ad, br[kk]);
                fma2(acc[i][2], ad, bs[kk]);
            }
        }
    }

    float sb0 = __ldg(skip_b + 2 * tc), sb1 = __ldg(skip_b + 2 * tc + 1);
    #pragma unroll
    for (int i = 0; i < 8; i++) {
        int gr = rowBase + tr * 8 + i;
        if (gr >= N) break;
        ((ull*)g_xl)[(size_t)gr * 32 + tc] = acc[i][0];
        ((ull*)g_xr)[(size_t)gr * 32 + tc] = acc[i][1];
        float lo, hi; unpack2(acc[i][2], lo, hi);
        float2 o; o.x = lo + sb0; o.y = hi + sb1;
        ((float2*)g_xs)[(size_t)gr * 32 + tc] = o;
    }
}

// ---------------- K2: per-dst online softmax + aggregate (1 warp / node) ----------------
__global__ __launch_bounds__(256) void k_edge(
    const float* __restrict__ att, const float* __restrict__ conv_bias, int N, int E)
{
    int gw = (blockIdx.x * blockDim.x + threadIdx.x) >> 5;
    if (gw >= N) return;
    int l = threadIdx.x & 31;
    int d = gw;

    const float2* xl2 = (const float2*)g_xl;
    float2 xr = __ldg((const float2*)g_xr + (size_t)d * 32 + l);
    float a0 = __ldg(att + 2 * l), a1 = __ldg(att + 2 * l + 1);

    float m = -3.4e38f, den = 0.f, s0 = 0.f, s1 = 0.f;
    int e = g_off[d];
    int end = (d + 1 < N) ? g_off[d + 1] : E;
    int src = d;                                   // self-loop processed first

    for (;;) {
        float2 v = __ldg(xl2 + (size_t)src * 32 + l);
        float t0 = v.x + xr.x, t1 = v.y + xr.y;
        t0 = t0 > 0.f ? t0 : 0.2f * t0;
        t1 = t1 > 0.f ? t1 : 0.2f * t1;
        float p = fmaf(t0, a0, t1 * a1);
        p += __shfl_xor_sync(0xffffffffu, p, 1);
        p += __shfl_xor_sync(0xffffffffu, p, 2);
        p += __shfl_xor_sync(0xffffffffu, p, 4);   // head-group (8 lanes) sum
        float nm = fmaxf(m, p);
        float c  = __expf(m - nm);                 // first iter: exp(-inf)=0
        float ex = __expf(p - nm);
        den = fmaf(den, c, ex);
        s0  = fmaf(s0, c, v.x * ex);
        s1  = fmaf(s1, c, v.y * ex);
        m = nm;
        if (e >= end) break;
        src = __ldg(&g_csr[e]);
        ++e;
    }

    float inv = 1.f / den;
    float2 o;
    o.x = fmaf(s0, inv, __ldg(conv_bias + 2 * l));
    o.y = fmaf(s1, inv, __ldg(conv_bias + 2 * l + 1));
    ((float2*)g_out)[(size_t)d * 32 + l] = o;
}

// ---------------- K3: per-graph sums + sumsq (single pass, run-length over sorted batch) ----
__global__ __launch_bounds__(256) void k_stats(const int* __restrict__ batch, int N)
{
    int gid = blockIdx.x * blockDim.x + threadIdx.x;
    int ch = gid & 63;
    int slot = gid >> 6;
    int n0 = slot * 32;
    if (n0 >= N) return;
    int n1 = min(n0 + 32, N);

    float aM = 0.f, qM = 0.f, aS = 0.f, qS = 0.f, ac = 0.f;
    int curg = batch[n0];
    for (int n = n0; n < n1; n++) {
        int g = batch[n];
        if (g != curg) {
            atomicAdd(&g_sumM[curg * 64 + ch], aM);
            atomicAdd(&g_sqM [curg * 64 + ch], qM);
            atomicAdd(&g_sumS[curg * 64 + ch], aS);
            atomicAdd(&g_sqS [curg * 64 + ch], qS);
            if (ch == 0) atomicAdd(&g_cnt[curg], ac);
            aM = qM = aS = qS = ac = 0.f; curg = g;
        }
        float vm = g_out[(size_t)n * 64 + ch];
        float vs = g_xs [(size_t)n * 64 + ch];
        aM += vm; qM = fmaf(vm, vm, qM);
        aS += vs; qS = fmaf(vs, vs, qS);
        ac += 1.f;
    }
    atomicAdd(&g_sumM[curg * 64 + ch], aM);
    atomicAdd(&g_sqM [curg * 64 + ch], qM);
    atomicAdd(&g_sumS[curg * 64 + ch], aS);
    atomicAdd(&g_sqS [curg * 64 + ch], qS);
    if (ch == 0) atomicAdd(&g_cnt[curg], ac);
}

// ---------------- K4: normalize + residual + ELU ----------------
__global__ __launch_bounds__(256) void k_final(
    const int* __restrict__ batch,
    const float* __restrict__ bn_w, const float* __restrict__ bn_b, const float* __restrict__ bn_ms,
    const float* __restrict__ sn_w, const float* __restrict__ sn_b, const float* __restrict__ sn_ms,
    float* __restrict__ out, int N)
{
    int i = blockIdx.x * blockDim.x + threadIdx.x;
    if (i >= N * 64) return;
    int n = i >> 6, ch = i & 63;
    int g = batch[n];
    float cnt = fmaxf(g_cnt[g], 1.f);
    float rinv = 1.f / cnt;
    float msM = bn_ms[ch], msS = sn_ms[ch];

    float meanM = g_sumM[g * 64 + ch] * rinv;
    float eqM   = g_sqM [g * 64 + ch] * rinv;
    float varM  = fmaxf(eqM - meanM * meanM * msM * (2.f - msM), 0.f);

    float meanS = g_sumS[g * 64 + ch] * rinv;
    float eqS   = g_sqS [g * 64 + ch] * rinv;
    float varS  = fmaxf(eqS - meanS * meanS * msS * (2.f - msS), 0.f);

    float cm = g_out[i] - meanM * msM;
    float cs = g_xs [i] - meanS * msS;
    float ym = bn_w[ch] * cm * rsqrtf(varM + 1e-5f) + bn_b[ch];
    float ys = sn_w[ch] * cs * rsqrtf(varS + 1e-5f) + sn_b[ch];
    float y = ym + ys;
    out[i] = (y > 0.f) ? y : expm1f(y);
}

// ---------------- launch ----------------
extern "C" void kernel_launch(void* const* d_in, const int* in_sizes, int n_in,
                              void* d_out, int out_size)
{
    const float* x         = (const float*)d_in[0];
    const int*   ei        = (const int*)d_in[1];
    const int*   batch     = (const int*)d_in[2];
    const float* Wl        = (const float*)d_in[3];
    const float* Wr        = (const float*)d_in[4];
    const float* att       = (const float*)d_in[5];
    const float* conv_bias = (const float*)d_in[6];
    const float* skip_W    = (const float*)d_in[7];
    const float* skip_b    = (const float*)d_in[8];
    const float* bn_w      = (const float*)d_in[9];
    const float* bn_b      = (const float*)d_in[10];
    const float* bn_ms     = (const float*)d_in[11];
    const float* sn_w      = (const float*)d_in[12];
    const float* sn_b      = (const float*)d_in[13];
    const float* sn_ms     = (const float*)d_in[14];
    float*       out       = (float*)d_out;

    int N  = in_sizes[0] / 128;
    int E  = in_sizes[1] / 2;
    int nb = (N + 1023) / 1024;

    k_init <<<(N + 255) / 256, 256>>>(N);
    k_hist <<<(E + 255) / 256, 256>>>(ei, E);
    k_scan1<<<nb, 1024>>>(N);
    k_scan2<<<1, 1024>>>(nb);
    k_scan3<<<(N + 255) / 256, 256>>>(N);
    k_fill <<<(E + 255) / 256, 256>>>(ei, E);

    k_gemm <<<(N + 63) / 64, 256>>>(x, Wl, Wr, skip_W, skip_b, N);

    {   // edge: 1 warp per node
        long long threads = (long long)N * 32;
        k_edge<<<(unsigned)((threads + 255) / 256), 256>>>(att, conv_bias, N, E);
    }
    {   // stats: 64 channels x 1 slot per 32 nodes
        int slots = (N + 31) / 32;
        long long threads = (long long)slots * 64;
        k_stats<<<(unsigned)((threads + 255) / 256), 256>>>(batch, N);
    }
    {   // final
        int total = N * 64;
        k_final<<<(total + 255) / 256, 256>>>(batch, bn_w, bn_b, bn_ms,
                                              sn_w, sn_b, sn_ms, out, N);
    }
}

// round 4
// speedup vs baseline: 1.9285x; 1.0644x over previous
#include <cuda_runtime.h>
#include <cuda_bf16.h>
#include <math.h>

#define N_MAX   100000
#define E_MAX   1600000
#define G_NUM   64

typedef unsigned long long ull;

// ---------------- scratch (device globals; no allocation) ----------------
__device__ __align__(16) float g_xl[N_MAX * 64];
__device__ __align__(16) float g_xr[N_MAX * 64];
__device__ __align__(16) float g_xs[N_MAX * 64];
__device__ __align__(16) float g_out[N_MAX * 64];
__device__ int   g_deg[N_MAX];
__device__ int   g_off[N_MAX];
__device__ int   g_cur[N_MAX];
__device__ int   g_csr[E_MAX];
__device__ int   g_bsum[1024];
__device__ float g_sumM[G_NUM * 64];
__device__ float g_sqM [G_NUM * 64];
__device__ float g_sumS[G_NUM * 64];
__device__ float g_sqS [G_NUM * 64];
__device__ float g_cnt [G_NUM];

// ---------------- f32x2 helpers ----------------
__device__ __forceinline__ ull pack_dup(float a) {
    ull r; asm("mov.b64 %0, {%1, %1};" : "=l"(r) : "f"(a)); return r;
}
__device__ __forceinline__ void fma2(ull& d, ull a, ull b) {
    asm("fma.rn.f32x2 %0, %1, %2, %0;" : "+l"(d) : "l"(a), "l"(b));
}
__device__ __forceinline__ void unpack2(ull v, float& lo, float& hi) {
    asm("mov.b64 {%0, %1}, %2;" : "=f"(lo), "=f"(hi) : "l"(v));
}

// ---------------- K0: init + degree histogram (merged) ----------------
__global__ void k_init_hist(const int* __restrict__ ei, int N, int E) {
    int i = blockIdx.x * blockDim.x + threadIdx.x;
    if (i < N) g_deg[i] = 0;
    if (i < G_NUM * 64) { g_sumM[i] = 0.f; g_sqM[i] = 0.f; g_sumS[i] = 0.f; g_sqS[i] = 0.f; }
    if (i < G_NUM) g_cnt[i] = 0.f;
}
__global__ void k_hist(const int* __restrict__ ei, int E) {
    int i = blockIdx.x * blockDim.x + threadIdx.x;
    if (i < E) atomicAdd(&g_deg[ei[E + i]], 1);
}

__global__ __launch_bounds__(1024) void k_scan1(int N) {
    __shared__ int s[1024];
    int tid = threadIdx.x;
    int i = blockIdx.x * 1024 + tid;
    int v = (i < N) ? g_deg[i] : 0;
    s[tid] = v;
    #pragma unroll
    for (int d = 1; d < 1024; d <<= 1) {
        __syncthreads();
        int t = (tid >= d) ? s[tid - d] : 0;
        __syncthreads();
        s[tid] += t;
    }
    __syncthreads();
    if (i < N) g_off[i] = s[tid] - v;
    if (tid == 1023) g_bsum[blockIdx.x] = s[1023];
}

__global__ __launch_bounds__(1024) void k_scan2(int nb) {
    __shared__ int s[1024];
    int tid = threadIdx.x;
    int v = (tid < nb) ? g_bsum[tid] : 0;
    s[tid] = v;
    #pragma unroll
    for (int d = 1; d < 1024; d <<= 1) {
        __syncthreads();
        int t = (tid >= d) ? s[tid - d] : 0;
        __syncthreads();
        s[tid] += t;
    }
    __syncthreads();
    if (tid < nb) g_bsum[tid] = s[tid] - v;
}

__global__ void k_scan3(int N) {
    int i = blockIdx.x * blockDim.x + threadIdx.x;
    if (i >= N) return;
    int o = g_off[i] + g_bsum[i >> 10];
    g_off[i] = o;
    g_cur[i] = o;
}

__global__ void k_fill(const int* __restrict__ ei, int E) {
    int i = blockIdx.x * blockDim.x + threadIdx.x;
    if (i >= E) return;
    int dst = ei[E + i];
    int pos = atomicAdd(&g_cur[dst], 1);
    g_csr[pos] = ei[i];
}

// ---------------- K1: fused GEMM via f32x2  [xl|xr|xs] = X @ [Wl|Wr|Ws] ----------------
__global__ __launch_bounds__(256) void k_gemm(
    const float* __restrict__ x,
    const float* __restrict__ Wl, const float* __restrict__ Wr,
    const float* __restrict__ Ws, const float* __restrict__ skip_b, int N)
{
    __shared__ float Xs[64 * 128];
    int tid = threadIdx.x;
    int rowBase = blockIdx.x * 64;

    const float4* xg = (const float4*)x;
    for (int i = tid; i < 64 * 32; i += 256) {
        int r = i >> 5, c4 = i & 31;
        int gr = rowBase + r;
        float4 v = (gr < N) ? __ldg(xg + (size_t)gr * 32 + c4) : make_float4(0.f, 0.f, 0.f, 0.f);
        ((float4*)Xs)[i] = v;
    }
    __syncthreads();

    int tr = tid >> 5, tc = tid & 31;
    const ull* wl64 = (const ull*)Wl;
    const ull* wr64 = (const ull*)Wr;
    const ull* ws64 = (const ull*)Ws;

    ull acc[8][3];
    #pragma unroll
    for (int i = 0; i < 8; i++)
        #pragma unroll
        for (int j = 0; j < 3; j++) acc[i][j] = 0ULL;

    for (int k = 0; k < 128; k += 4) {
        ull bl[4], br[4], bs[4];
        #pragma unroll
        for (int kk = 0; kk < 4; kk++) {
            bl[kk] = __ldg(wl64 + (k + kk) * 32 + tc);
            br[kk] = __ldg(wr64 + (k + kk) * 32 + tc);
            bs[kk] = __ldg(ws64 + (k + kk) * 32 + tc);
        }
        float4 av[8];
        #pragma unroll
        for (int i = 0; i < 8; i++)
            av[i] = *(const float4*)&Xs[(tr * 8 + i) * 128 + k];
        #pragma unroll
        for (int kk = 0; kk < 4; kk++) {
            #pragma unroll
            for (int i = 0; i < 8; i++) {
                float a = (kk == 0) ? av[i].x : (kk == 1) ? av[i].y : (kk == 2) ? av[i].z : av[i].w;
                ull ad = pack_dup(a);
                fma2(acc[i][0], ad, bl[kk]);
                fma2(acc[i][1], ad, br[kk]);
                fma2(acc[i][2], ad, bs[kk]);
            }
        }
    }

    float sb0 = __ldg(skip_b + 2 * tc), sb1 = __ldg(skip_b + 2 * tc + 1);
    #pragma unroll
    for (int i = 0; i < 8; i++) {
        int gr = rowBase + tr * 8 + i;
        if (gr >= N) break;
        ((ull*)g_xl)[(size_t)gr * 32 + tc] = acc[i][0];
        ((ull*)g_xr)[(size_t)gr * 32 + tc] = acc[i][1];
        float lo, hi; unpack2(acc[i][2], lo, hi);
        float2 o; o.x = lo + sb0; o.y = hi + sb1;
        ((float2*)g_xs)[(size_t)gr * 32 + tc] = o;
    }
}

// ---------------- K2: per-dst softmax-aggregate, no-max, 2 edges/warp, float4 ----------------
__global__ __launch_bounds__(256) void k_edge(
    const float* __restrict__ att, const float* __restrict__ conv_bias, int N, int E)
{
    int gw = (blockIdx.x * blockDim.x + threadIdx.x) >> 5;
    if (gw >= N) return;
    int lane = threadIdx.x & 31;
    int half = lane >> 4;            // 0 or 1
    int l = lane & 15;               // lane within half: float4 slot -> channels 4l..4l+3
    int d = gw;
    unsigned hmask = half ? 0xFFFF0000u : 0x0000FFFFu;

    const float4* xl4 = (const float4*)g_xl;
    float4 xr = __ldg((const float4*)g_xr + (size_t)d * 16 + l);
    float4 at = __ldg((const float4*)att + l);

    float den = 0.f, s0 = 0.f, s1 = 0.f, s2 = 0.f, s3 = 0.f;

    int e0  = g_off[d];
    int end = (d + 1 < N) ? g_off[d + 1] : E;
    int base = e0 + half;
    int count = end - base;                          // edges for this half
    count = (count > 0) ? ((count + 1) >> 1) : 0;

    #pragma unroll 2
    for (int it = -half; it < count; it++) {         // it==-0? half1 starts at it=-1 -> self-loop
        int src = (it < 0) ? d : __ldg(&g_csr[base + 2 * it]);
        float4 v = __ldg(xl4 + (size_t)src * 16 + l);
        float t0 = v.x + xr.x, t1 = v.y + xr.y, t2 = v.z + xr.z, t3 = v.w + xr.w;
        t0 = t0 > 0.f ? t0 : 0.2f * t0;
        t1 = t1 > 0.f ? t1 : 0.2f * t1;
        t2 = t2 > 0.f ? t2 : 0.2f * t2;
        t3 = t3 > 0.f ? t3 : 0.2f * t3;
        float p = fmaf(t0, at.x, fmaf(t1, at.y, fmaf(t2, at.z, t3 * at.w)));
        p += __shfl_xor_sync(hmask, p, 1);
        p += __shfl_xor_sync(hmask, p, 2);           // sum over 4-lane head group
        float ex = __expf(p);
        den += ex;
        s0 = fmaf(v.x, ex, s0);
        s1 = fmaf(v.y, ex, s1);
        s2 = fmaf(v.z, ex, s2);
        s3 = fmaf(v.w, ex, s3);
    }

    __syncwarp();
    den += __shfl_xor_sync(0xffffffffu, den, 16);
    s0  += __shfl_xor_sync(0xffffffffu, s0, 16);
    s1  += __shfl_xor_sync(0xffffffffu, s1, 16);
    s2  += __shfl_xor_sync(0xffffffffu, s2, 16);
    s3  += __shfl_xor_sync(0xffffffffu, s3, 16);

    if (half == 0) {
        float inv = 1.f / den;
        float4 cb = __ldg((const float4*)conv_bias + l);
        float4 o;
        o.x = fmaf(s0, inv, cb.x);
        o.y = fmaf(s1, inv, cb.y);
        o.z = fmaf(s2, inv, cb.z);
        o.w = fmaf(s3, inv, cb.w);
        ((float4*)g_out)[(size_t)d * 16 + l] = o;
    }
}

// ---------------- K3: per-graph sums + sumsq (single pass) ----------------
__global__ __launch_bounds__(256) void k_stats(const int* __restrict__ batch, int N)
{
    int gid = blockIdx.x * blockDim.x + threadIdx.x;
    int ch = gid & 63;
    int slot = gid >> 6;
    int n0 = slot * 32;
    if (n0 >= N) return;
    int n1 = min(n0 + 32, N);

    int gfirst = batch[n0], glast = batch[n1 - 1];
    if (gfirst == glast) {
        // fast path: whole slot in one graph, branch-free
        float aM = 0.f, qM = 0.f, aS = 0.f, qS = 0.f;
        #pragma unroll 4
        for (int n = n0; n < n1; n++) {
            float vm = g_out[(size_t)n * 64 + ch];
            float vs = g_xs [(size_t)n * 64 + ch];
            aM += vm; qM = fmaf(vm, vm, qM);
            aS += vs; qS = fmaf(vs, vs, qS);
        }
        atomicAdd(&g_sumM[gfirst * 64 + ch], aM);
        atomicAdd(&g_sqM [gfirst * 64 + ch], qM);
        atomicAdd(&g_sumS[gfirst * 64 + ch], aS);
        atomicAdd(&g_sqS [gfirst * 64 + ch], qS);
        if (ch == 0) atomicAdd(&g_cnt[gfirst], (float)(n1 - n0));
        return;
    }

    float aM = 0.f, qM = 0.f, aS = 0.f, qS = 0.f, ac = 0.f;
    int curg = gfirst;
    for (int n = n0; n < n1; n++) {
        int g = batch[n];
        if (g != curg) {
            atomicAdd(&g_sumM[curg * 64 + ch], aM);
            atomicAdd(&g_sqM [curg * 64 + ch], qM);
            atomicAdd(&g_sumS[curg * 64 + ch], aS);
            atomicAdd(&g_sqS [curg * 64 + ch], qS);
            if (ch == 0) atomicAdd(&g_cnt[curg], ac);
            aM = qM = aS = qS = ac = 0.f; curg = g;
        }
        float vm = g_out[(size_t)n * 64 + ch];
        float vs = g_xs [(size_t)n * 64 + ch];
        aM += vm; qM = fmaf(vm, vm, qM);
        aS += vs; qS = fmaf(vs, vs, qS);
        ac += 1.f;
    }
    atomicAdd(&g_sumM[curg * 64 + ch], aM);
    atomicAdd(&g_sqM [curg * 64 + ch], qM);
    atomicAdd(&g_sumS[curg * 64 + ch], aS);
    atomicAdd(&g_sqS [curg * 64 + ch], qS);
    if (ch == 0) atomicAdd(&g_cnt[curg], ac);
}

// ---------------- K4: normalize + residual + ELU (float4) ----------------
__global__ __launch_bounds__(256) void k_final(
    const int* __restrict__ batch,
    const float* __restrict__ bn_w, const float* __restrict__ bn_b, const float* __restrict__ bn_ms,
    const float* __restrict__ sn_w, const float* __restrict__ sn_b, const float* __restrict__ sn_ms,
    float* __restrict__ out, int N)
{
    int i = blockIdx.x * blockDim.x + threadIdx.x;   // one float4 per thread
    if (i >= N * 16) return;
    int n = i >> 4, q = i & 15;                      // q: float4 slot (channels 4q..4q+3)
    int g = batch[n];
    float cnt = fmaxf(g_cnt[g], 1.f);
    float rinv = 1.f / cnt;

    float4 vm4 = ((const float4*)g_out)[i];
    float4 vs4 = ((const float4*)g_xs)[i];
    float4 res;
    const float* pv = (const float*)&vm4;
    const float* ps = (const float*)&vs4;
    float* pr = (float*)&res;

    #pragma unroll
    for (int k = 0; k < 4; k++) {
        int ch = 4 * q + k;
        float msM = __ldg(bn_ms + ch), msS = __ldg(sn_ms + ch);
        float meanM = g_sumM[g * 64 + ch] * rinv;
        float eqM   = g_sqM [g * 64 + ch] * rinv;
        float varM  = fmaxf(eqM - meanM * meanM * msM * (2.f - msM), 0.f);
        float meanS = g_sumS[g * 64 + ch] * rinv;
        float eqS   = g_sqS [g * 64 + ch] * rinv;
        float varS  = fmaxf(eqS - meanS * meanS * msS * (2.f - msS), 0.f);

        float cm = pv[k] - meanM * msM;
        float cs = ps[k] - meanS * msS;
        float ym = __ldg(bn_w + ch) * cm * rsqrtf(varM + 1e-5f) + __ldg(bn_b + ch);
        float ys = __ldg(sn_w + ch) * cs * rsqrtf(varS + 1e-5f) + __ldg(sn_b + ch);
        float y = ym + ys;
        pr[k] = (y > 0.f) ? y : expm1f(y);
    }
    ((float4*)out)[i] = res;
}

// ---------------- launch ----------------
extern "C" void kernel_launch(void* const* d_in, const int* in_sizes, int n_in,
                              void* d_out, int out_size)
{
    const float* x         = (const float*)d_in[0];
    const int*   ei        = (const int*)d_in[1];
    const int*   batch     = (const int*)d_in[2];
    const float* Wl        = (const float*)d_in[3];
    const float* Wr        = (const float*)d_in[4];
    const float* att       = (const float*)d_in[5];
    const float* conv_bias = (const float*)d_in[6];
    const float* skip_W    = (const float*)d_in[7];
    const float* skip_b    = (const float*)d_in[8];
    const float* bn_w      = (const float*)d_in[9];
    const float* bn_b      = (const float*)d_in[10];
    const float* bn_ms     = (const float*)d_in[11];
    const float* sn_w      = (const float*)d_in[12];
    const float* sn_b      = (const float*)d_in[13];
    const float* sn_ms     = (const float*)d_in[14];
    float*       out       = (float*)d_out;

    int N  = in_sizes[0] / 128;
    int E  = in_sizes[1] / 2;
    int nb = (N + 1023) / 1024;

    k_init_hist<<<(N + 255) / 256, 256>>>(ei, N, E);
    k_hist <<<(E + 255) / 256, 256>>>(ei, E);
    k_scan1<<<nb, 1024>>>(N);
    k_scan2<<<1, 1024>>>(nb);
    k_scan3<<<(N + 255) / 256, 256>>>(N);
    k_fill <<<(E + 255) / 256, 256>>>(ei, E);

    k_gemm <<<(N + 63) / 64, 256>>>(x, Wl, Wr, skip_W, skip_b, N);

    {   // edge: 1 warp per node
        long long threads = (long long)N * 32;
        k_edge<<<(unsigned)((threads + 255) / 256), 256>>>(att, conv_bias, N, E);
    }
    {   // stats
        int slots = (N + 31) / 32;
        long long threads = (long long)slots * 64;
        k_stats<<<(unsigned)((threads + 255) / 256), 256>>>(batch, N);
    }
    {   // final
        long long total = (long long)N * 16;
        k_final<<<(unsigned)((total + 255) / 256), 256>>>(batch, bn_w, bn_b, bn_ms,
                                                          sn_w, sn_b, sn_ms, out, N);
    }
}

// round 5
// speedup vs baseline: 2.0210x; 1.0480x over previous
#include <cuda_runtime.h>
#include <cuda_bf16.h>
#include <math.h>

#define N_MAX   100000
#define E_MAX   1600000
#define G_NUM   64

typedef unsigned long long ull;

// ---------------- scratch (device globals; no allocation) ----------------
__device__ __align__(16) float g_xl[N_MAX * 64];
__device__ __align__(16) float g_xr[N_MAX * 64];
__device__ __align__(16) float g_xs[N_MAX * 64];
__device__ __align__(16) float g_out[N_MAX * 64];
__device__ int   g_deg[N_MAX];
__device__ int   g_off[N_MAX];
__device__ int   g_cur[N_MAX];
__device__ int   g_csr[E_MAX];
__device__ int   g_bsum[1024];
__device__ float g_sumM[G_NUM * 64];   // later reused: cM
__device__ float g_sqM [G_NUM * 64];   // later reused: C
__device__ float g_sumS[G_NUM * 64];   // later reused: cS
__device__ float g_sqS [G_NUM * 64];
__device__ float g_cnt [G_NUM];

// ---------------- f32x2 helpers ----------------
__device__ __forceinline__ ull pack_dup(float a) {
    ull r; asm("mov.b64 %0, {%1, %1};" : "=l"(r) : "f"(a)); return r;
}
__device__ __forceinline__ void fma2(ull& d, ull a, ull b) {
    asm("fma.rn.f32x2 %0, %1, %2, %0;" : "+l"(d) : "l"(a), "l"(b));
}
__device__ __forceinline__ void unpack2(ull v, float& lo, float& hi) {
    asm("mov.b64 {%0, %1}, %2;" : "=f"(lo), "=f"(hi) : "l"(v));
}

// ---------------- K0: init ----------------
__global__ void k_init(int N) {
    int i = blockIdx.x * blockDim.x + threadIdx.x;
    if (i < N) g_deg[i] = 0;
    if (i < G_NUM * 64) { g_sumM[i] = 0.f; g_sqM[i] = 0.f; g_sumS[i] = 0.f; g_sqS[i] = 0.f; }
    if (i < G_NUM) g_cnt[i] = 0.f;
}
__global__ void k_hist(const int* __restrict__ ei, int E) {
    int i = blockIdx.x * blockDim.x + threadIdx.x;
    if (i < E) atomicAdd(&g_deg[ei[E + i]], 1);
}

__global__ __launch_bounds__(1024) void k_scan1(int N) {
    __shared__ int s[1024];
    int tid = threadIdx.x;
    int i = blockIdx.x * 1024 + tid;
    int v = (i < N) ? g_deg[i] : 0;
    s[tid] = v;
    #pragma unroll
    for (int d = 1; d < 1024; d <<= 1) {
        __syncthreads();
        int t = (tid >= d) ? s[tid - d] : 0;
        __syncthreads();
        s[tid] += t;
    }
    __syncthreads();
    if (i < N) g_off[i] = s[tid] - v;
    if (tid == 1023) g_bsum[blockIdx.x] = s[1023];
}

__global__ __launch_bounds__(1024) void k_scan2(int nb) {
    __shared__ int s[1024];
    int tid = threadIdx.x;
    int v = (tid < nb) ? g_bsum[tid] : 0;
    s[tid] = v;
    #pragma unroll
    for (int d = 1; d < 1024; d <<= 1) {
        __syncthreads();
        int t = (tid >= d) ? s[tid - d] : 0;
        __syncthreads();
        s[tid] += t;
    }
    __syncthreads();
    if (tid < nb) g_bsum[tid] = s[tid] - v;
}

__global__ void k_scan3(int N) {
    int i = blockIdx.x * blockDim.x + threadIdx.x;
    if (i >= N) return;
    int o = g_off[i] + g_bsum[i >> 10];
    g_off[i] = o;
    g_cur[i] = o;
}

__global__ void k_fill(const int* __restrict__ ei, int E) {
    int i = blockIdx.x * blockDim.x + threadIdx.x;
    if (i >= E) return;
    int dst = ei[E + i];
    int pos = atomicAdd(&g_cur[dst], 1);
    g_csr[pos] = ei[i];
}

// ---------------- K1: fused GEMM via f32x2  [xl|xr|xs] = X @ [Wl|Wr|Ws] ----------------
__global__ __launch_bounds__(256) void k_gemm(
    const float* __restrict__ x,
    const float* __restrict__ Wl, const float* __restrict__ Wr,
    const float* __restrict__ Ws, const float* __restrict__ skip_b, int N)
{
    __shared__ float Xs[64 * 128];
    int tid = threadIdx.x;
    int rowBase = blockIdx.x * 64;

    const float4* xg = (const float4*)x;
    for (int i = tid; i < 64 * 32; i += 256) {
        int r = i >> 5, c4 = i & 31;
        int gr = rowBase + r;
        float4 v = (gr < N) ? __ldg(xg + (size_t)gr * 32 + c4) : make_float4(0.f, 0.f, 0.f, 0.f);
        ((float4*)Xs)[i] = v;
    }
    __syncthreads();

    int tr = tid >> 5, tc = tid & 31;
    const ull* wl64 = (const ull*)Wl;
    const ull* wr64 = (const ull*)Wr;
    const ull* ws64 = (const ull*)Ws;

    ull acc[8][3];
    #pragma unroll
    for (int i = 0; i < 8; i++)
        #pragma unroll
        for (int j = 0; j < 3; j++) acc[i][j] = 0ULL;

    for (int k = 0; k < 128; k += 4) {
        ull bl[4], br[4], bs[4];
        #pragma unroll
        for (int kk = 0; kk < 4; kk++) {
            bl[kk] = __ldg(wl64 + (k + kk) * 32 + tc);
            br[kk] = __ldg(wr64 + (k + kk) * 32 + tc);
            bs[kk] = __ldg(ws64 + (k + kk) * 32 + tc);
        }
        float4 av[8];
        #pragma unroll
        for (int i = 0; i < 8; i++)
            av[i] = *(const float4*)&Xs[(tr * 8 + i) * 128 + k];
        #pragma unroll
        for (int kk = 0; kk < 4; kk++) {
            #pragma unroll
            for (int i = 0; i < 8; i++) {
                float a = (kk == 0) ? av[i].x : (kk == 1) ? av[i].y : (kk == 2) ? av[i].z : av[i].w;
                ull ad = pack_dup(a);
                fma2(acc[i][0], ad, bl[kk]);
                fma2(acc[i][1], ad, br[kk]);
                fma2(acc[i][2], ad, bs[kk]);
            }
        }
    }

    float sb0 = __ldg(skip_b + 2 * tc), sb1 = __ldg(skip_b + 2 * tc + 1);
    #pragma unroll
    for (int i = 0; i < 8; i++) {
        int gr = rowBase + tr * 8 + i;
        if (gr >= N) break;
        ((ull*)g_xl)[(size_t)gr * 32 + tc] = acc[i][0];
        ((ull*)g_xr)[(size_t)gr * 32 + tc] = acc[i][1];
        float lo, hi; unpack2(acc[i][2], lo, hi);
        float2 o; o.x = lo + sb0; o.y = hi + sb1;
        ((float2*)g_xs)[(size_t)gr * 32 + tc] = o;
    }
}

// ---------------- K2: per-dst softmax-aggregate, no-max, 2 edges/warp, float4 ----------------
__global__ __launch_bounds__(256) void k_edge(
    const float* __restrict__ att, const float* __restrict__ conv_bias, int N, int E)
{
    int gw = (blockIdx.x * blockDim.x + threadIdx.x) >> 5;
    if (gw >= N) return;
    int lane = threadIdx.x & 31;
    int half = lane >> 4;            // 0 or 1
    int l = lane & 15;               // float4 slot -> channels 4l..4l+3
    int d = gw;
    unsigned hmask = half ? 0xFFFF0000u : 0x0000FFFFu;

    const float4* xl4 = (const float4*)g_xl;
    float4 xr = __ldg((const float4*)g_xr + (size_t)d * 16 + l);
    float4 at = __ldg((const float4*)att + l);

    float den = 0.f, s0 = 0.f, s1 = 0.f, s2 = 0.f, s3 = 0.f;

    int e0  = g_off[d];
    int end = (d + 1 < N) ? g_off[d + 1] : E;
    int nE  = end - e0;
    int cnt = (nE - half + 1) >> 1;      // edges for this half (counted loop)
    if (cnt < 0) cnt = 0;
    int base = e0 + half;

    // self-loop handled by half 1 (outside the main loop)
    if (half == 1) {
        float4 v = __ldg(xl4 + (size_t)d * 16 + l);
        float t0 = v.x + xr.x, t1 = v.y + xr.y, t2 = v.z + xr.z, t3 = v.w + xr.w;
        t0 = t0 > 0.f ? t0 : 0.2f * t0;
        t1 = t1 > 0.f ? t1 : 0.2f * t1;
        t2 = t2 > 0.f ? t2 : 0.2f * t2;
        t3 = t3 > 0.f ? t3 : 0.2f * t3;
        float p = fmaf(t0, at.x, fmaf(t1, at.y, fmaf(t2, at.z, t3 * at.w)));
        p += __shfl_xor_sync(hmask, p, 1);
        p += __shfl_xor_sync(hmask, p, 2);
        float ex = __expf(p);
        den += ex;
        s0 = fmaf(v.x, ex, s0);
        s1 = fmaf(v.y, ex, s1);
        s2 = fmaf(v.z, ex, s2);
        s3 = fmaf(v.w, ex, s3);
    } else {
        // keep both halves convergent through the shuffles above
        float p = 0.f;
        p += __shfl_xor_sync(hmask, p, 1);
        p += __shfl_xor_sync(hmask, p, 2);
    }

    #pragma unroll 4
    for (int it = 0; it < cnt; it++) {
        int src = __ldg(&g_csr[base + 2 * it]);
        float4 v = __ldg(xl4 + (size_t)src * 16 + l);
        float t0 = v.x + xr.x, t1 = v.y + xr.y, t2 = v.z + xr.z, t3 = v.w + xr.w;
        t0 = t0 > 0.f ? t0 : 0.2f * t0;
        t1 = t1 > 0.f ? t1 : 0.2f * t1;
        t2 = t2 > 0.f ? t2 : 0.2f * t2;
        t3 = t3 > 0.f ? t3 : 0.2f * t3;
        float p = fmaf(t0, at.x, fmaf(t1, at.y, fmaf(t2, at.z, t3 * at.w)));
        p += __shfl_xor_sync(hmask, p, 1);
        p += __shfl_xor_sync(hmask, p, 2);
        float ex = __expf(p);
        den += ex;
        s0 = fmaf(v.x, ex, s0);
        s1 = fmaf(v.y, ex, s1);
        s2 = fmaf(v.z, ex, s2);
        s3 = fmaf(v.w, ex, s3);
    }

    __syncwarp();
    den += __shfl_xor_sync(0xffffffffu, den, 16);
    s0  += __shfl_xor_sync(0xffffffffu, s0, 16);
    s1  += __shfl_xor_sync(0xffffffffu, s1, 16);
    s2  += __shfl_xor_sync(0xffffffffu, s2, 16);
    s3  += __shfl_xor_sync(0xffffffffu, s3, 16);

    if (half == 0) {
        float inv = 1.f / den;
        float4 cb = __ldg((const float4*)conv_bias + l);
        float4 o;
        o.x = fmaf(s0, inv, cb.x);
        o.y = fmaf(s1, inv, cb.y);
        o.z = fmaf(s2, inv, cb.z);
        o.w = fmaf(s3, inv, cb.w);
        ((float4*)g_out)[(size_t)d * 16 + l] = o;
    }
}

// ---------------- K3: per-graph sums + sumsq (single pass) ----------------
__global__ __launch_bounds__(256) void k_stats(const int* __restrict__ batch, int N)
{
    int gid = blockIdx.x * blockDim.x + threadIdx.x;
    int ch = gid & 63;
    int slot = gid >> 6;
    int n0 = slot * 32;
    if (n0 >= N) return;
    int n1 = min(n0 + 32, N);

    int gfirst = batch[n0], glast = batch[n1 - 1];
    if (gfirst == glast) {
        float aM = 0.f, qM = 0.f, aS = 0.f, qS = 0.f;
        #pragma unroll 4
        for (int n = n0; n < n1; n++) {
            float vm = g_out[(size_t)n * 64 + ch];
            float vs = g_xs [(size_t)n * 64 + ch];
            aM += vm; qM = fmaf(vm, vm, qM);
            aS += vs; qS = fmaf(vs, vs, qS);
        }
        atomicAdd(&g_sumM[gfirst * 64 + ch], aM);
        atomicAdd(&g_sqM [gfirst * 64 + ch], qM);
        atomicAdd(&g_sumS[gfirst * 64 + ch], aS);
        atomicAdd(&g_sqS [gfirst * 64 + ch], qS);
        if (ch == 0) atomicAdd(&g_cnt[gfirst], (float)(n1 - n0));
        return;
    }

    float aM = 0.f, qM = 0.f, aS = 0.f, qS = 0.f, ac = 0.f;
    int curg = gfirst;
    for (int n = n0; n < n1; n++) {
        int g = batch[n];
        if (g != curg) {
            atomicAdd(&g_sumM[curg * 64 + ch], aM);
            atomicAdd(&g_sqM [curg * 64 + ch], qM);
            atomicAdd(&g_sumS[curg * 64 + ch], aS);
            atomicAdd(&g_sqS [curg * 64 + ch], qS);
            if (ch == 0) atomicAdd(&g_cnt[curg], ac);
            aM = qM = aS = qS = ac = 0.f; curg = g;
        }
        float vm = g_out[(size_t)n * 64 + ch];
        float vs = g_xs [(size_t)n * 64 + ch];
        aM += vm; qM = fmaf(vm, vm, qM);
        aS += vs; qS = fmaf(vs, vs, qS);
        ac += 1.f;
    }
    atomicAdd(&g_sumM[curg * 64 + ch], aM);
    atomicAdd(&g_sqM [curg * 64 + ch], qM);
    atomicAdd(&g_sumS[curg * 64 + ch], aS);
    atomicAdd(&g_sqS [curg * 64 + ch], qS);
    if (ch == 0) atomicAdd(&g_cnt[curg], ac);
}

// ---------------- K3b: precompute per-(graph,channel) affine coeffs ----------------
// y = cM*vm + cS*vs + C   (overwrites g_sumM<-cM, g_sumS<-cS, g_sqM<-C)
__global__ void k_prec(
    const float* __restrict__ bn_w, const float* __restrict__ bn_b, const float* __restrict__ bn_ms,
    const float* __restrict__ sn_w, const float* __restrict__ sn_b, const float* __restrict__ sn_ms)
{
    int i = blockIdx.x * blockDim.x + threadIdx.x;
    if (i >= G_NUM * 64) return;
    int g = i >> 6, ch = i & 63;
    float cntv = fmaxf(g_cnt[g], 1.f);
    float rinv = 1.f / cntv;
    float msM = bn_ms[ch], msS = sn_ms[ch];

    float meanM = g_sumM[i] * rinv;
    float eqM   = g_sqM [i] * rinv;
    float varM  = fmaxf(eqM - meanM * meanM * msM * (2.f - msM), 0.f);
    float meanS = g_sumS[i] * rinv;
    float eqS   = g_sqS [i] * rinv;
    float varS  = fmaxf(eqS - meanS * meanS * msS * (2.f - msS), 0.f);

    float cM = bn_w[ch] * rsqrtf(varM + 1e-5f);
    float cS = sn_w[ch] * rsqrtf(varS + 1e-5f);
    float C  = bn_b[ch] + sn_b[ch] - cM * meanM * msM - cS * meanS * msS;
    g_sumM[i] = cM;
    g_sumS[i] = cS;
    g_sqM [i] = C;
}

// ---------------- K4: y = cM*vm + cS*vs + C, then ELU (float4) ----------------
__global__ __launch_bounds__(256) void k_final(
    const int* __restrict__ batch, float* __restrict__ out, int N)
{
    int i = blockIdx.x * blockDim.x + threadIdx.x;   // one float4 per thread
    if (i >= N * 16) return;
    int n = i >> 4, q = i & 15;
    int g = batch[n];

    float4 cM = ((const float4*)g_sumM)[g * 16 + q];
    float4 cS = ((const float4*)g_sumS)[g * 16 + q];
    float4 C  = ((const float4*)g_sqM )[g * 16 + q];
    float4 vm = ((const float4*)g_out)[i];
    float4 vs = ((const float4*)g_xs)[i];

    float4 res;
    float y;
    y = fmaf(cM.x, vm.x, fmaf(cS.x, vs.x, C.x)); res.x = (y > 0.f) ? y : (__expf(y) - 1.f);
    y = fmaf(cM.y, vm.y, fmaf(cS.y, vs.y, C.y)); res.y = (y > 0.f) ? y : (__expf(y) - 1.f);
    y = fmaf(cM.z, vm.z, fmaf(cS.z, vs.z, C.z)); res.z = (y > 0.f) ? y : (__expf(y) - 1.f);
    y = fmaf(cM.w, vm.w, fmaf(cS.w, vs.w, C.w)); res.w = (y > 0.f) ? y : (__expf(y) - 1.f);
    ((float4*)out)[i] = res;
}

// ---------------- launch ----------------
extern "C" void kernel_launch(void* const* d_in, const int* in_sizes, int n_in,
                              void* d_out, int out_size)
{
    const float* x         = (const float*)d_in[0];
    const int*   ei        = (const int*)d_in[1];
    const int*   batch     = (const int*)d_in[2];
    const float* Wl        = (const float*)d_in[3];
    const float* Wr        = (const float*)d_in[4];
    const float* att       = (const float*)d_in[5];
    const float* conv_bias = (const float*)d_in[6];
    const float* skip_W    = (const float*)d_in[7];
    const float* skip_b    = (const float*)d_in[8];
    const float* bn_w      = (const float*)d_in[9];
    const float* bn_b      = (const float*)d_in[10];
    const float* bn_ms     = (const float*)d_in[11];
    const float* sn_w      = (const float*)d_in[12];
    const float* sn_b      = (const float*)d_in[13];
    const float* sn_ms     = (const float*)d_in[14];
    float*       out       = (float*)d_out;

    int N  = in_sizes[0] / 128;
    int E  = in_sizes[1] / 2;
    int nb = (N + 1023) / 1024;

    k_init <<<(N + 255) / 256, 256>>>(N);                    // 1
    k_hist <<<(E + 255) / 256, 256>>>(ei, E);                // 2
    k_scan1<<<nb, 1024>>>(N);                                // 3
    k_gemm <<<(N + 63) / 64, 256>>>(x, Wl, Wr, skip_W, skip_b, N);  // 4 (profiled slot)
    k_scan2<<<1, 1024>>>(nb);                                // 5
    k_scan3<<<(N + 255) / 256, 256>>>(N);                    // 6
    k_fill <<<(E + 255) / 256, 256>>>(ei, E);                // 7

    {   // 8: edge, 1 warp per node
        long long threads = (long long)N * 32;
        k_edge<<<(unsigned)((threads + 255) / 256), 256>>>(att, conv_bias, N, E);
    }
    {   // 9: stats
        int slots = (N + 31) / 32;
        long long threads = (long long)slots * 64;
        k_stats<<<(unsigned)((threads + 255) / 256), 256>>>(batch, N);
    }
    k_prec<<<(G_NUM * 64 + 255) / 256, 256>>>(bn_w, bn_b, bn_ms, sn_w, sn_b, sn_ms);  // 10
    {   // 11: final
        long long total = (long long)N * 16;
        k_final<<<(unsigned)((total + 255) / 256), 256>>>(batch, out, N);
    }
}

// round 7
// speedup vs baseline: 2.3162x; 1.1461x over previous
#include <cuda_runtime.h>
#include <cuda_bf16.h>
#include <cstdint>
#include <math.h>

#define N_MAX   100000
#define E_MAX   1600000
#define G_NUM   64

typedef unsigned long long ull;

// ---------------- scratch (device globals; no allocation) ----------------
__device__ __align__(16) float g_xl[N_MAX * 64];
__device__ __align__(16) float g_xr[N_MAX * 64];
__device__ __align__(16) float g_xs[N_MAX * 64];
__device__ __align__(16) float g_out[N_MAX * 64];
__device__ int   g_deg[N_MAX];
__device__ int   g_off[N_MAX];
__device__ int   g_cur[N_MAX];
__device__ int   g_csr[E_MAX];
__device__ int   g_bsum[1024];
__device__ float g_sumM[G_NUM * 64];   // later reused: cM
__device__ float g_sqM [G_NUM * 64];   // later reused: C
__device__ float g_sumS[G_NUM * 64];   // later reused: cS
__device__ float g_sqS [G_NUM * 64];
__device__ float g_cnt [G_NUM];

// ---------------- f32x2 helpers ----------------
__device__ __forceinline__ ull pack_dup(float a) {
    ull r; asm("mov.b64 %0, {%1, %1};" : "=l"(r) : "f"(a)); return r;
}
__device__ __forceinline__ void fma2(ull& d, ull a, ull b) {
    asm("fma.rn.f32x2 %0, %1, %2, %0;" : "+l"(d) : "l"(a), "l"(b));
}
__device__ __forceinline__ void unpack2(ull v, float& lo, float& hi) {
    asm("mov.b64 {%0, %1}, %2;" : "=f"(lo), "=f"(hi) : "l"(v));
}

// ---------------- K0: init ----------------
__global__ void k_init(int N) {
    int i = blockIdx.x * blockDim.x + threadIdx.x;
    if (i < N) g_deg[i] = 0;
    if (i < G_NUM * 64) { g_sumM[i] = 0.f; g_sqM[i] = 0.f; g_sumS[i] = 0.f; g_sqS[i] = 0.f; }
    if (i < G_NUM) g_cnt[i] = 0.f;
}
__global__ void k_hist(const int* __restrict__ ei, int E) {
    int i = blockIdx.x * blockDim.x + threadIdx.x;
    if (i < E) atomicAdd(&g_deg[ei[E + i]], 1);
}

__global__ __launch_bounds__(1024) void k_scan1(int N) {
    __shared__ int s[1024];
    int tid = threadIdx.x;
    int i = blockIdx.x * 1024 + tid;
    int v = (i < N) ? g_deg[i] : 0;
    s[tid] = v;
    #pragma unroll
    for (int d = 1; d < 1024; d <<= 1) {
        __syncthreads();
        int t = (tid >= d) ? s[tid - d] : 0;
        __syncthreads();
        s[tid] += t;
    }
    __syncthreads();
    if (i < N) g_off[i] = s[tid] - v;
    if (tid == 1023) g_bsum[blockIdx.x] = s[1023];
}

__global__ __launch_bounds__(1024) void k_scan2(int nb) {
    __shared__ int s[1024];
    int tid = threadIdx.x;
    int v = (tid < nb) ? g_bsum[tid] : 0;
    s[tid] = v;
    #pragma unroll
    for (int d = 1; d < 1024; d <<= 1) {
        __syncthreads();
        int t = (tid >= d) ? s[tid - d] : 0;
        __syncthreads();
        s[tid] += t;
    }
    __syncthreads();
    if (tid < nb) g_bsum[tid] = s[tid] - v;
}

__global__ void k_scan3(int N) {
    int i = blockIdx.x * blockDim.x + threadIdx.x;
    if (i >= N) return;
    int o = g_off[i] + g_bsum[i >> 10];
    g_off[i] = o;
    g_cur[i] = o;
}

__global__ void k_fill(const int* __restrict__ ei, int E) {
    int i = blockIdx.x * blockDim.x + threadIdx.x;
    if (i >= E) return;
    int dst = ei[E + i];
    int pos = atomicAdd(&g_cur[dst], 1);
    g_csr[pos] = ei[i];
}

// ---------------- K1: fused GEMM, cp.async double-buffered weights ----------------
#define KCH 8                 // k per chunk
#define NCH (128 / KCH)       // 16 chunks
__global__ __launch_bounds__(256) void k_gemm(
    const float* __restrict__ x,
    const float* __restrict__ Wl, const float* __restrict__ Wr,
    const float* __restrict__ Ws, const float* __restrict__ skip_b, int N)
{
    __shared__ float Xs[64 * 128];            // 32 KB
    __shared__ ull   Wsm[2][KCH][96];         // 12 KB (double-buffered weight chunk)
    int tid = threadIdx.x;
    int rowBase = blockIdx.x * 64;

    const ull* wsrc0 = (const ull*)Wl;
    const ull* wsrc1 = (const ull*)Wr;
    const ull* wsrc2 = (const ull*)Ws;

    // --- issue chunk 0 before anything else ---
    {
        const int c = 0, buf = 0;
        for (int s = tid; s < KCH * 48; s += 256) {   // 384 float4 slots per chunk
            int mat = s >> 7;                          // 128 f4 per matrix (8k x 16f4)
            int rem = s & 127;
            int k = rem >> 4;
            int f4 = rem & 15;
            const ull* src = (mat == 0 ? wsrc0 : mat == 1 ? wsrc1 : wsrc2)
                             + (size_t)(c * KCH + k) * 32 + f4 * 2;
            unsigned int da = (unsigned int)__cvta_generic_to_shared(&Wsm[buf][k][mat * 32 + f4 * 2]);
            asm volatile("cp.async.cg.shared.global [%0], [%1], 16;" :: "r"(da), "l"(src));
        }
        asm volatile("cp.async.commit_group;");
    }

    // --- X tile load (overlaps with chunk 0 in flight) ---
    const float4* xg = (const float4*)x;
    for (int i = tid; i < 64 * 32; i += 256) {
        int r = i >> 5, c4 = i & 31;
        int gr = rowBase + r;
        float4 v = (gr < N) ? __ldg(xg + (size_t)gr * 32 + c4) : make_float4(0.f, 0.f, 0.f, 0.f);
        ((float4*)Xs)[i] = v;
    }

    int tr = tid >> 5, tc = tid & 31;
    ull acc[8][3];
    #pragma unroll
    for (int i = 0; i < 8; i++)
        #pragma unroll
        for (int j = 0; j < 3; j++) acc[i][j] = 0ULL;

    for (int c = 0; c < NCH; c++) {
        int buf = c & 1;
        if (c + 1 < NCH) {
            int nb2 = buf ^ 1;
            for (int s = tid; s < KCH * 48; s += 256) {
                int mat = s >> 7;
                int rem = s & 127;
                int k = rem >> 4;
                int f4 = rem & 15;
                const ull* src = (mat == 0 ? wsrc0 : mat == 1 ? wsrc1 : wsrc2)
                                 + (size_t)((c + 1) * KCH + k) * 32 + f4 * 2;
                unsigned int da = (unsigned int)__cvta_generic_to_shared(&Wsm[nb2][k][mat * 32 + f4 * 2]);
                asm volatile("cp.async.cg.shared.global [%0], [%1], 16;" :: "r"(da), "l"(src));
            }
            asm volatile("cp.async.commit_group;");
            asm volatile("cp.async.wait_group 1;");
        } else {
            asm volatile("cp.async.wait_group 0;");
        }
        __syncthreads();

        #pragma unroll
        for (int k0 = 0; k0 < KCH; k0 += 4) {
            ull bl[4], br[4], bs[4];
            #pragma unroll
            for (int kk = 0; kk < 4; kk++) {
                bl[kk] = Wsm[buf][k0 + kk][tc];
                br[kk] = Wsm[buf][k0 + kk][32 + tc];
                bs[kk] = Wsm[buf][k0 + kk][64 + tc];
            }
            float4 av[8];
            #pragma unroll
            for (int i = 0; i < 8; i++)
                av[i] = *(const float4*)&Xs[(tr * 8 + i) * 128 + c * KCH + k0];
            #pragma unroll
            for (int kk = 0; kk < 4; kk++) {
                #pragma unroll
                for (int i = 0; i < 8; i++) {
                    float a = (kk == 0) ? av[i].x : (kk == 1) ? av[i].y : (kk == 2) ? av[i].z : av[i].w;
                    ull ad = pack_dup(a);
                    fma2(acc[i][0], ad, bl[kk]);
                    fma2(acc[i][1], ad, br[kk]);
                    fma2(acc[i][2], ad, bs[kk]);
                }
            }
        }
        __syncthreads();
    }

    float sb0 = __ldg(skip_b + 2 * tc), sb1 = __ldg(skip_b + 2 * tc + 1);
    #pragma unroll
    for (int i = 0; i < 8; i++) {
        int gr = rowBase + tr * 8 + i;
        if (gr >= N) break;
        ((ull*)g_xl)[(size_t)gr * 32 + tc] = acc[i][0];
        ((ull*)g_xr)[(size_t)gr * 32 + tc] = acc[i][1];
        float lo, hi; unpack2(acc[i][2], lo, hi);
        float2 o; o.x = lo + sb0; o.y = hi + sb1;
        ((float2*)g_xs)[(size_t)gr * 32 + tc] = o;
    }
}

// ---------------- K2: per-dst softmax-aggregate, no-max, 2 edges/warp, float4 ----------------
__global__ __launch_bounds__(256) void k_edge(
    const float* __restrict__ att, const float* __restrict__ conv_bias, int N, int E)
{
    int gw = (blockIdx.x * blockDim.x + threadIdx.x) >> 5;
    if (gw >= N) return;
    int lane = threadIdx.x & 31;
    int half = lane >> 4;            // 0 or 1
    int l = lane & 15;               // float4 slot -> channels 4l..4l+3
    int d = gw;
    unsigned hmask = half ? 0xFFFF0000u : 0x0000FFFFu;

    const float4* xl4 = (const float4*)g_xl;
    float4 xr = __ldg((const float4*)g_xr + (size_t)d * 16 + l);
    float4 at = __ldg((const float4*)att + l);

    float den = 0.f, s0 = 0.f, s1 = 0.f, s2 = 0.f, s3 = 0.f;

    int e0  = g_off[d];
    int end = (d + 1 < N) ? g_off[d + 1] : E;
    int nE  = end - e0;
    int cnt = (nE - half + 1) >> 1;
    if (cnt < 0) cnt = 0;
    int base = e0 + half;

    if (half == 1) {
        float4 v = __ldg(xl4 + (size_t)d * 16 + l);
        float t0 = v.x + xr.x, t1 = v.y + xr.y, t2 = v.z + xr.z, t3 = v.w + xr.w;
        t0 = t0 > 0.f ? t0 : 0.2f * t0;
        t1 = t1 > 0.f ? t1 : 0.2f * t1;
        t2 = t2 > 0.f ? t2 : 0.2f * t2;
        t3 = t3 > 0.f ? t3 : 0.2f * t3;
        float p = fmaf(t0, at.x, fmaf(t1, at.y, fmaf(t2, at.z, t3 * at.w)));
        p += __shfl_xor_sync(hmask, p, 1);
        p += __shfl_xor_sync(hmask, p, 2);
        float ex = __expf(p);
        den += ex;
        s0 = fmaf(v.x, ex, s0);
        s1 = fmaf(v.y, ex, s1);
        s2 = fmaf(v.z, ex, s2);
        s3 = fmaf(v.w, ex, s3);
    } else {
        float p = 0.f;
        p += __shfl_xor_sync(hmask, p, 1);
        p += __shfl_xor_sync(hmask, p, 2);
    }

    #pragma unroll 4
    for (int it = 0; it < cnt; it++) {
        int src = __ldg(&g_csr[base + 2 * it]);
        float4 v = __ldg(xl4 + (size_t)src * 16 + l);
        float t0 = v.x + xr.x, t1 = v.y + xr.y, t2 = v.z + xr.z, t3 = v.w + xr.w;
        t0 = t0 > 0.f ? t0 : 0.2f * t0;
        t1 = t1 > 0.f ? t1 : 0.2f * t1;
        t2 = t2 > 0.f ? t2 : 0.2f * t2;
        t3 = t3 > 0.f ? t3 : 0.2f * t3;
        float p = fmaf(t0, at.x, fmaf(t1, at.y, fmaf(t2, at.z, t3 * at.w)));
        p += __shfl_xor_sync(hmask, p, 1);
        p += __shfl_xor_sync(hmask, p, 2);
        float ex = __expf(p);
        den += ex;
        s0 = fmaf(v.x, ex, s0);
        s1 = fmaf(v.y, ex, s1);
        s2 = fmaf(v.z, ex, s2);
        s3 = fmaf(v.w, ex, s3);
    }

    __syncwarp();
    den += __shfl_xor_sync(0xffffffffu, den, 16);
    s0  += __shfl_xor_sync(0xffffffffu, s0, 16);
    s1  += __shfl_xor_sync(0xffffffffu, s1, 16);
    s2  += __shfl_xor_sync(0xffffffffu, s2, 16);
    s3  += __shfl_xor_sync(0xffffffffu, s3, 16);

    if (half == 0) {
        float inv = 1.f / den;
        float4 cb = __ldg((const float4*)conv_bias + l);
        float4 o;
        o.x = fmaf(s0, inv, cb.x);
        o.y = fmaf(s1, inv, cb.y);
        o.z = fmaf(s2, inv, cb.z);
        o.w = fmaf(s3, inv, cb.w);
        ((float4*)g_out)[(size_t)d * 16 + l] = o;
    }
}

// ---------------- K3: per-graph sums + sumsq (single pass) ----------------
__global__ __launch_bounds__(256) void k_stats(const int* __restrict__ batch, int N)
{
    int gid = blockIdx.x * blockDim.x + threadIdx.x;
    int ch = gid & 63;
    int slot = gid >> 6;
    int n0 = slot * 32;
    if (n0 >= N) return;
    int n1 = min(n0 + 32, N);

    int gfirst = batch[n0], glast = batch[n1 - 1];
    if (gfirst == glast) {
        float aM = 0.f, qM = 0.f, aS = 0.f, qS = 0.f;
        #pragma unroll 4
        for (int n = n0; n < n1; n++) {
            float vm = g_out[(size_t)n * 64 + ch];
            float vs = g_xs [(size_t)n * 64 + ch];
            aM += vm; qM = fmaf(vm, vm, qM);
            aS += vs; qS = fmaf(vs, vs, qS);
        }
        atomicAdd(&g_sumM[gfirst * 64 + ch], aM);
        atomicAdd(&g_sqM [gfirst * 64 + ch], qM);
        atomicAdd(&g_sumS[gfirst * 64 + ch], aS);
        atomicAdd(&g_sqS [gfirst * 64 + ch], qS);
        if (ch == 0) atomicAdd(&g_cnt[gfirst], (float)(n1 - n0));
        return;
    }

    float aM = 0.f, qM = 0.f, aS = 0.f, qS = 0.f, ac = 0.f;
    int curg = gfirst;
    for (int n = n0; n < n1; n++) {
        int g = batch[n];
        if (g != curg) {
            atomicAdd(&g_sumM[curg * 64 + ch], aM);
            atomicAdd(&g_sqM [curg * 64 + ch], qM);
            atomicAdd(&g_sumS[curg * 64 + ch], aS);
            atomicAdd(&g_sqS [curg * 64 + ch], qS);
            if (ch == 0) atomicAdd(&g_cnt[curg], ac);
            aM = qM = aS = qS = ac = 0.f; curg = g;
        }
        float vm = g_out[(size_t)n * 64 + ch];
        float vs = g_xs [(size_t)n * 64 + ch];
        aM += vm; qM = fmaf(vm, vm, qM);
        aS += vs; qS = fmaf(vs, vs, qS);
        ac += 1.f;
    }
    atomicAdd(&g_sumM[curg * 64 + ch], aM);
    atomicAdd(&g_sqM [curg * 64 + ch], qM);
    atomicAdd(&g_sumS[curg * 64 + ch], aS);
    atomicAdd(&g_sqS [curg * 64 + ch], qS);
    if (ch == 0) atomicAdd(&g_cnt[curg], ac);
}

// ---------------- K3b: precompute per-(graph,channel) affine coeffs ----------------
__global__ void k_prec(
    const float* __restrict__ bn_w, const float* __restrict__ bn_b, const float* __restrict__ bn_ms,
    const float* __restrict__ sn_w, const float* __restrict__ sn_b, const float* __restrict__ sn_ms)
{
    int i = blockIdx.x * blockDim.x + threadIdx.x;
    if (i >= G_NUM * 64) return;
    int g = i >> 6, ch = i & 63;
    float cntv = fmaxf(g_cnt[g], 1.f);
    float rinv = 1.f / cntv;
    float msM = bn_ms[ch], msS = sn_ms[ch];

    float meanM = g_sumM[i] * rinv;
    float eqM   = g_sqM [i] * rinv;
    float varM  = fmaxf(eqM - meanM * meanM * msM * (2.f - msM), 0.f);
    float meanS = g_sumS[i] * rinv;
    float eqS   = g_sqS [i] * rinv;
    float varS  = fmaxf(eqS - meanS * meanS * msS * (2.f - msS), 0.f);

    float cM = bn_w[ch] * rsqrtf(varM + 1e-5f);
    float cS = sn_w[ch] * rsqrtf(varS + 1e-5f);
    float C  = bn_b[ch] + sn_b[ch] - cM * meanM * msM - cS * meanS * msS;
    g_sumM[i] = cM;
    g_sumS[i] = cS;
    g_sqM [i] = C;
}

// ---------------- K4: y = cM*vm + cS*vs + C, then ELU (float4) ----------------
__global__ __launch_bounds__(256) void k_final(
    const int* __restrict__ batch, float* __restrict__ out, int N)
{
    int i = blockIdx.x * blockDim.x + threadIdx.x;
    if (i >= N * 16) return;
    int n = i >> 4, q = i & 15;
    int g = batch[n];

    float4 cM = ((const float4*)g_sumM)[g * 16 + q];
    float4 cS = ((const float4*)g_sumS)[g * 16 + q];
    float4 C  = ((const float4*)g_sqM )[g * 16 + q];
    float4 vm = ((const float4*)g_out)[i];
    float4 vs = ((const float4*)g_xs)[i];

    float4 res;
    float y;
    y = fmaf(cM.x, vm.x, fmaf(cS.x, vs.x, C.x)); res.x = (y > 0.f) ? y : (__expf(y) - 1.f);
    y = fmaf(cM.y, vm.y, fmaf(cS.y, vs.y, C.y)); res.y = (y > 0.f) ? y : (__expf(y) - 1.f);
    y = fmaf(cM.z, vm.z, fmaf(cS.z, vs.z, C.z)); res.z = (y > 0.f) ? y : (__expf(y) - 1.f);
    y = fmaf(cM.w, vm.w, fmaf(cS.w, vs.w, C.w)); res.w = (y > 0.f) ? y : (__expf(y) - 1.f);
    ((float4*)out)[i] = res;
}

// ---------------- launch ----------------
extern "C" void kernel_launch(void* const* d_in, const int* in_sizes, int n_in,
                              void* d_out, int out_size)
{
    const float* x         = (const float*)d_in[0];
    const int*   ei        = (const int*)d_in[1];
    const int*   batch     = (const int*)d_in[2];
    const float* Wl        = (const float*)d_in[3];
    const float* Wr        = (const float*)d_in[4];
    const float* att       = (const float*)d_in[5];
    const float* conv_bias = (const float*)d_in[6];
    const float* skip_W    = (const float*)d_in[7];
    const float* skip_b    = (const float*)d_in[8];
    const float* bn_w      = (const float*)d_in[9];
    const float* bn_b      = (const float*)d_in[10];
    const float* bn_ms     = (const float*)d_in[11];
    const float* sn_w      = (const float*)d_in[12];
    const float* sn_b      = (const float*)d_in[13];
    const float* sn_ms     = (const float*)d_in[14];
    float*       out       = (float*)d_out;

    int N  = in_sizes[0] / 128;
    int E  = in_sizes[1] / 2;
    int nb = (N + 1023) / 1024;

    k_init <<<(N + 255) / 256, 256>>>(N);                    // 1
    k_hist <<<(E + 255) / 256, 256>>>(ei, E);                // 2
    k_scan1<<<nb, 1024>>>(N);                                // 3
    k_gemm <<<(N + 63) / 64, 256>>>(x, Wl, Wr, skip_W, skip_b, N);  // 4 (profiled slot)
    k_scan2<<<1, 1024>>>(nb);                                // 5
    k_scan3<<<(N + 255) / 256, 256>>>(N);                    // 6
    k_fill <<<(E + 255) / 256, 256>>>(ei, E);                // 7

    {   // 8: edge, 1 warp per node
        long long threads = (long long)N * 32;
        k_edge<<<(unsigned)((threads + 255) / 256), 256>>>(att, conv_bias, N, E);
    }
    {   // 9: stats
        int slots = (N + 31) / 32;
        long long threads = (long long)slots * 64;
        k_stats<<<(unsigned)((threads + 255) / 256), 256>>>(batch, N);
    }
    k_prec<<<(G_NUM * 64 + 255) / 256, 256>>>(bn_w, bn_b, bn_ms, sn_w, sn_b, sn_ms);  // 10
    {   // 11: final
        long long total = (long long)N * 16;
        k_final<<<(unsigned)((total + 255) / 256), 256>>>(batch, out, N);
    }
}

// round 8
// speedup vs baseline: 2.3309x; 1.0064x over previous
#include <cuda_runtime.h>
#include <cuda_bf16.h>
#include <cstdint>
#include <math.h>

#define N_MAX   100000
#define E_MAX   1600000
#define G_NUM   64

typedef unsigned long long ull;

// ---------------- scratch (device globals; no allocation) ----------------
__device__ __align__(16) float g_xl[N_MAX * 64];
__device__ __align__(16) float g_xr[N_MAX * 64];
__device__ __align__(16) float g_xs[N_MAX * 64];
__device__ __align__(16) float g_out[N_MAX * 64];
__device__ int   g_deg[N_MAX];
__device__ int   g_off[N_MAX];
__device__ int   g_cur[N_MAX];
__device__ int   g_csr[E_MAX];
__device__ int   g_bsum[1024];
__device__ float g_sumM[G_NUM * 64];   // later reused: cM
__device__ float g_sqM [G_NUM * 64];   // later reused: C
__device__ float g_sumS[G_NUM * 64];   // later reused: cS
__device__ float g_sqS [G_NUM * 64];
__device__ float g_cnt [G_NUM];

// ---------------- f32x2 helpers ----------------
__device__ __forceinline__ ull pack_dup(float a) {
    ull r; asm("mov.b64 %0, {%1, %1};" : "=l"(r) : "f"(a)); return r;
}
__device__ __forceinline__ void fma2(ull& d, ull a, ull b) {
    asm("fma.rn.f32x2 %0, %1, %2, %0;" : "+l"(d) : "l"(a), "l"(b));
}
__device__ __forceinline__ void unpack2(ull v, float& lo, float& hi) {
    asm("mov.b64 {%0, %1}, %2;" : "=f"(lo), "=f"(hi) : "l"(v));
}

// ---------------- K0: init ----------------
__global__ void k_init(int N) {
    int i = blockIdx.x * blockDim.x + threadIdx.x;
    if (i < N) g_deg[i] = 0;
    if (i < G_NUM * 64) { g_sumM[i] = 0.f; g_sqM[i] = 0.f; g_sumS[i] = 0.f; g_sqS[i] = 0.f; }
    if (i < G_NUM) g_cnt[i] = 0.f;
}
__global__ void k_hist(const int* __restrict__ ei, int E) {
    int i = blockIdx.x * blockDim.x + threadIdx.x;
    if (i < E) atomicAdd(&g_deg[ei[E + i]], 1);
}

__global__ __launch_bounds__(1024) void k_scan1(int N) {
    __shared__ int s[1024];
    int tid = threadIdx.x;
    int i = blockIdx.x * 1024 + tid;
    int v = (i < N) ? g_deg[i] : 0;
    s[tid] = v;
    #pragma unroll
    for (int d = 1; d < 1024; d <<= 1) {
        __syncthreads();
        int t = (tid >= d) ? s[tid - d] : 0;
        __syncthreads();
        s[tid] += t;
    }
    __syncthreads();
    if (i < N) g_off[i] = s[tid] - v;
    if (tid == 1023) g_bsum[blockIdx.x] = s[1023];
}

__global__ __launch_bounds__(1024) void k_scan2(int nb) {
    __shared__ int s[1024];
    int tid = threadIdx.x;
    int v = (tid < nb) ? g_bsum[tid] : 0;
    s[tid] = v;
    #pragma unroll
    for (int d = 1; d < 1024; d <<= 1) {
        __syncthreads();
        int t = (tid >= d) ? s[tid - d] : 0;
        __syncthreads();
        s[tid] += t;
    }
    __syncthreads();
    if (tid < nb) g_bsum[tid] = s[tid] - v;
}

__global__ void k_scan3(int N) {
    int i = blockIdx.x * blockDim.x + threadIdx.x;
    if (i >= N) return;
    int o = g_off[i] + g_bsum[i >> 10];
    g_off[i] = o;
    g_cur[i] = o;
}

__global__ void k_fill(const int* __restrict__ ei, int E) {
    int i = blockIdx.x * blockDim.x + threadIdx.x;
    if (i >= E) return;
    int dst = ei[E + i];
    int pos = atomicAdd(&g_cur[dst], 1);
    g_csr[pos] = ei[i];
}

// ---------------- K1: fused GEMM, cp.async chunks + register-pipelined LDS ----------------
#define KCH 16                // k per chunk
#define NCH (128 / KCH)       // 8 chunks
__global__ __launch_bounds__(256, 2) void k_gemm(
    const float* __restrict__ x,
    const float* __restrict__ Wl, const float* __restrict__ Wr,
    const float* __restrict__ Ws, const float* __restrict__ skip_b, int N)
{
    __shared__ float Xs[64 * 128];            // 32 KB
    __shared__ ull   Wsm[2][KCH][96];         // 24 KB (double-buffered weight chunk)
    int tid = threadIdx.x;
    int rowBase = blockIdx.x * 64;

    const ull* wsrc0 = (const ull*)Wl;
    const ull* wsrc1 = (const ull*)Wr;
    const ull* wsrc2 = (const ull*)Ws;

    // --- issue chunk 0 ---
    {
        for (int s = tid; s < KCH * 48; s += 256) {    // 768 float4 slots
            int mat = s / 256;                          // 256 f4 per matrix (16k x 16f4)
            int rem = s & 255;
            int k = rem >> 4;
            int f4 = rem & 15;
            const ull* src = (mat == 0 ? wsrc0 : mat == 1 ? wsrc1 : wsrc2)
                             + (size_t)k * 32 + f4 * 2;
            unsigned int da = (unsigned int)__cvta_generic_to_shared(&Wsm[0][k][mat * 32 + f4 * 2]);
            asm volatile("cp.async.cg.shared.global [%0], [%1], 16;" :: "r"(da), "l"(src));
        }
        asm volatile("cp.async.commit_group;");
    }

    // --- X tile load (overlaps chunk 0 in flight) ---
    const float4* xg = (const float4*)x;
    for (int i = tid; i < 64 * 32; i += 256) {
        int r = i >> 5, c4 = i & 31;
        int gr = rowBase + r;
        float4 v = (gr < N) ? __ldg(xg + (size_t)gr * 32 + c4) : make_float4(0.f, 0.f, 0.f, 0.f);
        ((float4*)Xs)[i] = v;
    }

    int tr = tid >> 5, tc = tid & 31;
    ull acc[8][3];
    #pragma unroll
    for (int i = 0; i < 8; i++)
        #pragma unroll
        for (int j = 0; j < 3; j++) acc[i][j] = 0ULL;

    for (int c = 0; c < NCH; c++) {
        int buf = c & 1;
        if (c + 1 < NCH) {
            int nb2 = buf ^ 1;
            for (int s = tid; s < KCH * 48; s += 256) {
                int mat = s / 256;
                int rem = s & 255;
                int k = rem >> 4;
                int f4 = rem & 15;
                const ull* src = (mat == 0 ? wsrc0 : mat == 1 ? wsrc1 : wsrc2)
                                 + (size_t)((c + 1) * KCH + k) * 32 + f4 * 2;
                unsigned int da = (unsigned int)__cvta_generic_to_shared(&Wsm[nb2][k][mat * 32 + f4 * 2]);
                asm volatile("cp.async.cg.shared.global [%0], [%1], 16;" :: "r"(da), "l"(src));
            }
            asm volatile("cp.async.commit_group;");
            asm volatile("cp.async.wait_group 1;");
        } else {
            asm volatile("cp.async.wait_group 0;");
        }
        __syncthreads();

        // register-pipelined weight fragments: prefetch step k0+4 while computing k0
        ull wA[12];
        #pragma unroll
        for (int kk = 0; kk < 4; kk++) {
            wA[kk]     = Wsm[buf][kk][tc];
            wA[4 + kk] = Wsm[buf][kk][32 + tc];
            wA[8 + kk] = Wsm[buf][kk][64 + tc];
        }
        #pragma unroll
        for (int k0 = 0; k0 < KCH; k0 += 4) {
            ull wB[12];
            if (k0 + 4 < KCH) {
                #pragma unroll
                for (int kk = 0; kk < 4; kk++) {
                    wB[kk]     = Wsm[buf][k0 + 4 + kk][tc];
                    wB[4 + kk] = Wsm[buf][k0 + 4 + kk][32 + tc];
                    wB[8 + kk] = Wsm[buf][k0 + 4 + kk][64 + tc];
                }
            }
            // two row-groups of 4 to cap register pressure
            #pragma unroll
            for (int grp = 0; grp < 2; grp++) {
                float4 av[4];
                #pragma unroll
                for (int i = 0; i < 4; i++)
                    av[i] = *(const float4*)&Xs[(tr * 8 + grp * 4 + i) * 128 + c * KCH + k0];
                #pragma unroll
                for (int kk = 0; kk < 4; kk++) {
                    #pragma unroll
                    for (int i = 0; i < 4; i++) {
                        float a = (kk == 0) ? av[i].x : (kk == 1) ? av[i].y : (kk == 2) ? av[i].z : av[i].w;
                        ull ad = pack_dup(a);
                        int row = grp * 4 + i;
                        fma2(acc[row][0], ad, wA[kk]);
                        fma2(acc[row][1], ad, wA[4 + kk]);
                        fma2(acc[row][2], ad, wA[8 + kk]);
                    }
                }
            }
            if (k0 + 4 < KCH) {
                #pragma unroll
                for (int j = 0; j < 12; j++) wA[j] = wB[j];
            }
        }
        __syncthreads();
    }

    float sb0 = __ldg(skip_b + 2 * tc), sb1 = __ldg(skip_b + 2 * tc + 1);
    #pragma unroll
    for (int i = 0; i < 8; i++) {
        int gr = rowBase + tr * 8 + i;
        if (gr >= N) break;
        ((ull*)g_xl)[(size_t)gr * 32 + tc] = acc[i][0];
        ((ull*)g_xr)[(size_t)gr * 32 + tc] = acc[i][1];
        float lo, hi; unpack2(acc[i][2], lo, hi);
        float2 o; o.x = lo + sb0; o.y = hi + sb1;
        ((float2*)g_xs)[(size_t)gr * 32 + tc] = o;
    }
}

// ---------------- K2: per-dst softmax-aggregate, no-max, 2 edges/warp, float4 ----------------
__global__ __launch_bounds__(256) void k_edge(
    const float* __restrict__ att, const float* __restrict__ conv_bias, int N, int E)
{
    int gw = (blockIdx.x * blockDim.x + threadIdx.x) >> 5;
    if (gw >= N) return;
    int lane = threadIdx.x & 31;
    int half = lane >> 4;            // 0 or 1
    int l = lane & 15;               // float4 slot -> channels 4l..4l+3
    int d = gw;
    unsigned hmask = half ? 0xFFFF0000u : 0x0000FFFFu;

    const float4* xl4 = (const float4*)g_xl;
    float4 xr = __ldg((const float4*)g_xr + (size_t)d * 16 + l);
    float4 at = __ldg((const float4*)att + l);

    float den = 0.f, s0 = 0.f, s1 = 0.f, s2 = 0.f, s3 = 0.f;

    int e0  = g_off[d];
    int end = (d + 1 < N) ? g_off[d + 1] : E;
    int nE  = end - e0;
    int cnt = (nE - half + 1) >> 1;
    if (cnt < 0) cnt = 0;
    int base = e0 + half;

    if (half == 1) {
        float4 v = __ldg(xl4 + (size_t)d * 16 + l);
        float t0 = v.x + xr.x, t1 = v.y + xr.y, t2 = v.z + xr.z, t3 = v.w + xr.w;
        t0 = t0 > 0.f ? t0 : 0.2f * t0;
        t1 = t1 > 0.f ? t1 : 0.2f * t1;
        t2 = t2 > 0.f ? t2 : 0.2f * t2;
        t3 = t3 > 0.f ? t3 : 0.2f * t3;
        float p = fmaf(t0, at.x, fmaf(t1, at.y, fmaf(t2, at.z, t3 * at.w)));
        p += __shfl_xor_sync(hmask, p, 1);
        p += __shfl_xor_sync(hmask, p, 2);
        float ex = __expf(p);
        den += ex;
        s0 = fmaf(v.x, ex, s0);
        s1 = fmaf(v.y, ex, s1);
        s2 = fmaf(v.z, ex, s2);
        s3 = fmaf(v.w, ex, s3);
    } else {
        float p = 0.f;
        p += __shfl_xor_sync(hmask, p, 1);
        p += __shfl_xor_sync(hmask, p, 2);
    }

    #pragma unroll 4
    for (int it = 0; it < cnt; it++) {
        int src = __ldg(&g_csr[base + 2 * it]);
        float4 v = __ldg(xl4 + (size_t)src * 16 + l);
        float t0 = v.x + xr.x, t1 = v.y + xr.y, t2 = v.z + xr.z, t3 = v.w + xr.w;
        t0 = t0 > 0.f ? t0 : 0.2f * t0;
        t1 = t1 > 0.f ? t1 : 0.2f * t1;
        t2 = t2 > 0.f ? t2 : 0.2f * t2;
        t3 = t3 > 0.f ? t3 : 0.2f * t3;
        float p = fmaf(t0, at.x, fmaf(t1, at.y, fmaf(t2, at.z, t3 * at.w)));
        p += __shfl_xor_sync(hmask, p, 1);
        p += __shfl_xor_sync(hmask, p, 2);
        float ex = __expf(p);
        den += ex;
        s0 = fmaf(v.x, ex, s0);
        s1 = fmaf(v.y, ex, s1);
        s2 = fmaf(v.z, ex, s2);
        s3 = fmaf(v.w, ex, s3);
    }

    __syncwarp();
    den += __shfl_xor_sync(0xffffffffu, den, 16);
    s0  += __shfl_xor_sync(0xffffffffu, s0, 16);
    s1  += __shfl_xor_sync(0xffffffffu, s1, 16);
    s2  += __shfl_xor_sync(0xffffffffu, s2, 16);
    s3  += __shfl_xor_sync(0xffffffffu, s3, 16);

    if (half == 0) {
        float inv = 1.f / den;
        float4 cb = __ldg((const float4*)conv_bias + l);
        float4 o;
        o.x = fmaf(s0, inv, cb.x);
        o.y = fmaf(s1, inv, cb.y);
        o.z = fmaf(s2, inv, cb.z);
        o.w = fmaf(s3, inv, cb.w);
        ((float4*)g_out)[(size_t)d * 16 + l] = o;
    }
}

// ---------------- K3: per-graph sums + sumsq (single pass) ----------------
__global__ __launch_bounds__(256) void k_stats(const int* __restrict__ batch, int N)
{
    int gid = blockIdx.x * blockDim.x + threadIdx.x;
    int ch = gid & 63;
    int slot = gid >> 6;
    int n0 = slot * 32;
    if (n0 >= N) return;
    int n1 = min(n0 + 32, N);

    int gfirst = batch[n0], glast = batch[n1 - 1];
    if (gfirst == glast) {
        float aM = 0.f, qM = 0.f, aS = 0.f, qS = 0.f;
        #pragma unroll 4
        for (int n = n0; n < n1; n++) {
            float vm = g_out[(size_t)n * 64 + ch];
            float vs = g_xs [(size_t)n * 64 + ch];
            aM += vm; qM = fmaf(vm, vm, qM);
            aS += vs; qS = fmaf(vs, vs, qS);
        }
        atomicAdd(&g_sumM[gfirst * 64 + ch], aM);
        atomicAdd(&g_sqM [gfirst * 64 + ch], qM);
        atomicAdd(&g_sumS[gfirst * 64 + ch], aS);
        atomicAdd(&g_sqS [gfirst * 64 + ch], qS);
        if (ch == 0) atomicAdd(&g_cnt[gfirst], (float)(n1 - n0));
        return;
    }

    float aM = 0.f, qM = 0.f, aS = 0.f, qS = 0.f, ac = 0.f;
    int curg = gfirst;
    for (int n = n0; n < n1; n++) {
        int g = batch[n];
        if (g != curg) {
            atomicAdd(&g_sumM[curg * 64 + ch], aM);
            atomicAdd(&g_sqM [curg * 64 + ch], qM);
            atomicAdd(&g_sumS[curg * 64 + ch], aS);
            atomicAdd(&g_sqS [curg * 64 + ch], qS);
            if (ch == 0) atomicAdd(&g_cnt[curg], ac);
            aM = qM = aS = qS = ac = 0.f; curg = g;
        }
        float vm = g_out[(size_t)n * 64 + ch];
        float vs = g_xs [(size_t)n * 64 + ch];
        aM += vm; qM = fmaf(vm, vm, qM);
        aS += vs; qS = fmaf(vs, vs, qS);
        ac += 1.f;
    }
    atomicAdd(&g_sumM[curg * 64 + ch], aM);
    atomicAdd(&g_sqM [curg * 64 + ch], qM);
    atomicAdd(&g_sumS[curg * 64 + ch], aS);
    atomicAdd(&g_sqS [curg * 64 + ch], qS);
    if (ch == 0) atomicAdd(&g_cnt[curg], ac);
}

// ---------------- K3b: precompute per-(graph,channel) affine coeffs ----------------
__global__ void k_prec(
    const float* __restrict__ bn_w, const float* __restrict__ bn_b, const float* __restrict__ bn_ms,
    const float* __restrict__ sn_w, const float* __restrict__ sn_b, const float* __restrict__ sn_ms)
{
    int i = blockIdx.x * blockDim.x + threadIdx.x;
    if (i >= G_NUM * 64) return;
    int g = i >> 6, ch = i & 63;
    float cntv = fmaxf(g_cnt[g], 1.f);
    float rinv = 1.f / cntv;
    float msM = bn_ms[ch], msS = sn_ms[ch];

    float meanM = g_sumM[i] * rinv;
    float eqM   = g_sqM [i] * rinv;
    float varM  = fmaxf(eqM - meanM * meanM * msM * (2.f - msM), 0.f);
    float meanS = g_sumS[i] * rinv;
    float eqS   = g_sqS [i] * rinv;
    float varS  = fmaxf(eqS - meanS * meanS * msS * (2.f - msS), 0.f);

    float cM = bn_w[ch] * rsqrtf(varM + 1e-5f);
    float cS = sn_w[ch] * rsqrtf(varS + 1e-5f);
    float C  = bn_b[ch] + sn_b[ch] - cM * meanM * msM - cS * meanS * msS;
    g_sumM[i] = cM;
    g_sumS[i] = cS;
    g_sqM [i] = C;
}

// ---------------- K4: y = cM*vm + cS*vs + C, then ELU (float4) ----------------
__global__ __launch_bounds__(256) void k_final(
    const int* __restrict__ batch, float* __restrict__ out, int N)
{
    int i = blockIdx.x * blockDim.x + threadIdx.x;
    if (i >= N * 16) return;
    int n = i >> 4, q = i & 15;
    int g = batch[n];

    float4 cM = ((const float4*)g_sumM)[g * 16 + q];
    float4 cS = ((const float4*)g_sumS)[g * 16 + q];
    float4 C  = ((const float4*)g_sqM )[g * 16 + q];
    float4 vm = ((const float4*)g_out)[i];
    float4 vs = ((const float4*)g_xs)[i];

    float4 res;
    float y;
    y = fmaf(cM.x, vm.x, fmaf(cS.x, vs.x, C.x)); res.x = (y > 0.f) ? y : (__expf(y) - 1.f);
    y = fmaf(cM.y, vm.y, fmaf(cS.y, vs.y, C.y)); res.y = (y > 0.f) ? y : (__expf(y) - 1.f);
    y = fmaf(cM.z, vm.z, fmaf(cS.z, vs.z, C.z)); res.z = (y > 0.f) ? y : (__expf(y) - 1.f);
    y = fmaf(cM.w, vm.w, fmaf(cS.w, vs.w, C.w)); res.w = (y > 0.f) ? y : (__expf(y) - 1.f);
    ((float4*)out)[i] = res;
}

// ---------------- launch ----------------
extern "C" void kernel_launch(void* const* d_in, const int* in_sizes, int n_in,
                              void* d_out, int out_size)
{
    const float* x         = (const float*)d_in[0];
    const int*   ei        = (const int*)d_in[1];
    const int*   batch     = (const int*)d_in[2];
    const float* Wl        = (const float*)d_in[3];
    const float* Wr        = (const float*)d_in[4];
    const float* att       = (const float*)d_in[5];
    const float* conv_bias = (const float*)d_in[6];
    const float* skip_W    = (const float*)d_in[7];
    const float* skip_b    = (const float*)d_in[8];
    const float* bn_w      = (const float*)d_in[9];
    const float* bn_b      = (const float*)d_in[10];
    const float* bn_ms     = (const float*)d_in[11];
    const float* sn_w      = (const float*)d_in[12];
    const float* sn_b      = (const float*)d_in[13];
    const float* sn_ms     = (const float*)d_in[14];
    float*       out       = (float*)d_out;

    int N  = in_sizes[0] / 128;
    int E  = in_sizes[1] / 2;
    int nb = (N + 1023) / 1024;

    k_init <<<(N + 255) / 256, 256>>>(N);                    // 1
    k_hist <<<(E + 255) / 256, 256>>>(ei, E);                // 2
    k_scan1<<<nb, 1024>>>(N);                                // 3
    k_gemm <<<(N + 63) / 64, 256>>>(x, Wl, Wr, skip_W, skip_b, N);  // 4 (profiled slot)
    k_scan2<<<1, 1024>>>(nb);                                // 5
    k_scan3<<<(N + 255) / 256, 256>>>(N);                    // 6
    k_fill <<<(E + 255) / 256, 256>>>(ei, E);                // 7

    {   // 8: edge, 1 warp per node
        long long threads = (long long)N * 32;
        k_edge<<<(unsigned)((threads + 255) / 256), 256>>>(att, conv_bias, N, E);
    }
    {   // 9: stats
        int slots = (N + 31) / 32;
        long long threads = (long long)slots * 64;
        k_stats<<<(unsigned)((threads + 255) / 256), 256>>>(batch, N);
    }
    k_prec<<<(G_NUM * 64 + 255) / 256, 256>>>(bn_w, bn_b, bn_ms, sn_w, sn_b, sn_ms);  // 10
    {   // 11: final
        long long total = (long long)N * 16;
        k_final<<<(unsigned)((total + 255) / 256), 256>>>(batch, out, N);
    }
}